// round 1
// baseline (speedup 1.0000x reference)
#include <cuda_runtime.h>
#include <cstdint>
#include <math.h>

#define L_SEQ 4096
#define D_MODEL 1536
#define N_HEADS 12
#define HEAD_DIM 128

// Scratch (device globals; allocation-free per harness rules)
__device__ float g_q[L_SEQ * D_MODEL];
__device__ float g_k[L_SEQ * D_MODEL];
__device__ float g_v[L_SEQ * D_MODEL];
__device__ float g_att[L_SEQ * D_MODEL];

__device__ __forceinline__ uint32_t f2tf(float f) {
    uint32_t u;
    asm("cvt.rna.tf32.f32 %0, %1;" : "=r"(u) : "f"(f));
    return u;
}

__device__ __forceinline__ void mma_tf32(float* c, const uint32_t* a, const uint32_t* b) {
    asm volatile(
        "mma.sync.aligned.m16n8k8.row.col.f32.tf32.tf32.f32 "
        "{%0,%1,%2,%3}, {%4,%5,%6,%7}, {%8,%9}, {%0,%1,%2,%3};"
        : "+f"(c[0]), "+f"(c[1]), "+f"(c[2]), "+f"(c[3])
        : "r"(a[0]), "r"(a[1]), "r"(a[2]), "r"(a[3]), "r"(b[0]), "r"(b[1]));
}

// ============================================================================
// GEMM: C[M,N] = A[M,K] @ B[N,K]^T + bias[N]   (tf32 mma, fp32 accum)
// Tiles: 128x128x32, 256 threads (8 warps, 4x2), warp tile 32x64.
// ============================================================================
__global__ __launch_bounds__(256) void gemm_nt_bias(
    const float* __restrict__ A, const float* __restrict__ B,
    const float* __restrict__ bias, float* __restrict__ C,
    int M, int N, int K)
{
    __shared__ uint32_t As[128][36];  // pad 4 -> conflict-free fragment loads
    __shared__ uint32_t Bs[128][36];

    const int tid = threadIdx.x;
    const int wid = tid >> 5, lane = tid & 31;
    const int g = lane >> 2, t = lane & 3;
    const int wm = wid >> 1, wn = wid & 1;
    const int bm = blockIdx.y * 128, bn = blockIdx.x * 128;

    float acc[2][8][4];
    #pragma unroll
    for (int mi = 0; mi < 2; mi++)
        #pragma unroll
        for (int nj = 0; nj < 8; nj++)
            #pragma unroll
            for (int e = 0; e < 4; e++) acc[mi][nj][e] = 0.f;

    const int lrow = tid >> 3;        // 0..31
    const int lcol = (tid & 7) * 4;   // 0..28

    for (int k0 = 0; k0 < K; k0 += 32) {
        __syncthreads();
        #pragma unroll
        for (int r = 0; r < 128; r += 32) {
            float4 av = *(const float4*)(A + (size_t)(bm + lrow + r) * K + k0 + lcol);
            uint4 ua;
            ua.x = f2tf(av.x); ua.y = f2tf(av.y); ua.z = f2tf(av.z); ua.w = f2tf(av.w);
            *(uint4*)&As[lrow + r][lcol] = ua;
            float4 bv = *(const float4*)(B + (size_t)(bn + lrow + r) * K + k0 + lcol);
            uint4 ub;
            ub.x = f2tf(bv.x); ub.y = f2tf(bv.y); ub.z = f2tf(bv.z); ub.w = f2tf(bv.w);
            *(uint4*)&Bs[lrow + r][lcol] = ub;
        }
        __syncthreads();

        #pragma unroll
        for (int kk = 0; kk < 4; kk++) {
            uint32_t a[2][4], b[8][2];
            #pragma unroll
            for (int mi = 0; mi < 2; mi++) {
                int row = wm * 32 + mi * 16 + g;
                a[mi][0] = As[row][kk * 8 + t];
                a[mi][1] = As[row + 8][kk * 8 + t];
                a[mi][2] = As[row][kk * 8 + t + 4];
                a[mi][3] = As[row + 8][kk * 8 + t + 4];
            }
            #pragma unroll
            for (int nj = 0; nj < 8; nj++) {
                int col = wn * 64 + nj * 8 + g;
                b[nj][0] = Bs[col][kk * 8 + t];
                b[nj][1] = Bs[col][kk * 8 + t + 4];
            }
            #pragma unroll
            for (int mi = 0; mi < 2; mi++)
                #pragma unroll
                for (int nj = 0; nj < 8; nj++)
                    mma_tf32(acc[mi][nj], a[mi], b[nj]);
        }
    }

    #pragma unroll
    for (int mi = 0; mi < 2; mi++) {
        #pragma unroll
        for (int nj = 0; nj < 8; nj++) {
            int row = bm + wm * 32 + mi * 16 + g;
            int col = bn + wn * 64 + nj * 8 + t * 2;
            float b0 = bias[col], b1 = bias[col + 1];
            C[(size_t)row * N + col]           = acc[mi][nj][0] + b0;
            C[(size_t)row * N + col + 1]       = acc[mi][nj][1] + b1;
            C[(size_t)(row + 8) * N + col]     = acc[mi][nj][2] + b0;
            C[(size_t)(row + 8) * N + col + 1] = acc[mi][nj][3] + b1;
        }
    }
}

// ============================================================================
// Fused RMS-norm (over D=1536) + RoPE (per head, 64 pairs, 22/21/21 f/h/w split)
// grid = (L, 2): y==0 -> q, y==1 -> k.  256 threads/block.
// ============================================================================
__global__ __launch_bounds__(256) void rmsnorm_rope(
    float* __restrict__ q, float* __restrict__ k,
    const float* __restrict__ gq, const float* __restrict__ gk,
    const int* __restrict__ grid_sizes,
    const float* __restrict__ fcos, const float* __restrict__ fsin)
{
    const int row = blockIdx.x;
    const bool isK = (blockIdx.y != 0);
    float* p = (isK ? g_k : g_q) + (size_t)row * D_MODEL;
    (void)q; (void)k;
    const float* gam = isK ? gk : gq;

    float ss = 0.f;
    for (int i = threadIdx.x; i < D_MODEL; i += 256) {
        float v = p[i];
        ss += v * v;
    }
    __shared__ float red[8];
    #pragma unroll
    for (int o = 16; o; o >>= 1) ss += __shfl_xor_sync(0xffffffffu, ss, o);
    if ((threadIdx.x & 31) == 0) red[threadIdx.x >> 5] = ss;
    __syncthreads();
    __shared__ float s_rms;
    if (threadIdx.x == 0) {
        float tot = 0.f;
        #pragma unroll
        for (int i = 0; i < 8; i++) tot += red[i];
        s_rms = rsqrtf(tot / (float)D_MODEL + 1e-6f);
    }
    __syncthreads();
    const float rms = s_rms;

    const int f = grid_sizes[0], h = grid_sizes[1], w = grid_sizes[2];
    const int sl = f * h * w;
    if (row < sl) {
        const int fi = row / (h * w);
        const int rem = row % (h * w);
        const int hi = rem / w, wi = rem % w;
        for (int pp = threadIdx.x; pp < N_HEADS * 64; pp += 256) {
            const int head = pp >> 6;
            const int j = pp & 63;
            const int pos = (j < 22) ? fi : ((j < 43) ? hi : wi);
            const float co = fcos[pos * 64 + j];
            const float si = fsin[pos * 64 + j];
            const int ci = head * HEAD_DIM + 2 * j;
            const float xr = p[ci] * rms * gam[ci];
            const float xi = p[ci + 1] * rms * gam[ci + 1];
            p[ci]     = xr * co - xi * si;
            p[ci + 1] = xr * si + xi * co;
        }
    } else {
        for (int i = threadIdx.x; i < D_MODEL; i += 256) p[i] = p[i] * rms * gam[i];
    }
}

// ============================================================================
// Flash attention: BM=64 queries x BN=64 keys, d=128. tf32 mma for QK^T and PV.
// 128 threads (4 warps); each warp owns 16 query rows. Online softmax in fp32.
// Smem: Qs 64x132 | Ks 64x132 | Vs 64x136 | Ps 64x68 (tf32 words) = 117 KB.
// ============================================================================
#define QS_STR 132
#define KS_STR 132
#define VS_STR 136
#define PS_STR 68
#define FA_SMEM ((64 * (QS_STR + KS_STR + VS_STR + PS_STR)) * 4)

__global__ __launch_bounds__(128) void flash_attn(
    const float* __restrict__ q, const float* __restrict__ k,
    const float* __restrict__ v, float* __restrict__ o,
    const int* __restrict__ seq_lens)
{
    extern __shared__ uint32_t sm[];
    uint32_t* Qs = sm;
    uint32_t* Ks = Qs + 64 * QS_STR;
    uint32_t* Vs = Ks + 64 * KS_STR;
    uint32_t* Ps = Vs + 64 * VS_STR;

    const int tid = threadIdx.x, wid = tid >> 5, lane = tid & 31;
    const int g = lane >> 2, t = lane & 3;
    const int q0 = blockIdx.x * 64;
    const int head = blockIdx.y;
    const int seqlen = seq_lens[0];
    const float scale = 0.08838834764831845f;  // 1/sqrt(128)

    // Load Q tile (fold in softmax scale)
    for (int i = tid; i < 64 * 32; i += 128) {
        int r = i >> 5, c4 = (i & 31) * 4;
        float4 vq = *(const float4*)(q + (size_t)(q0 + r) * D_MODEL + head * HEAD_DIM + c4);
        uint4 u;
        u.x = f2tf(vq.x * scale); u.y = f2tf(vq.y * scale);
        u.z = f2tf(vq.z * scale); u.w = f2tf(vq.w * scale);
        *(uint4*)&Qs[r * QS_STR + c4] = u;
    }

    float m0 = -INFINITY, m1 = -INFINITY, l0 = 0.f, l1 = 0.f;
    float O[16][4];
    #pragma unroll
    for (int nj = 0; nj < 16; nj++)
        #pragma unroll
        for (int e = 0; e < 4; e++) O[nj][e] = 0.f;

    const int rowA = wid * 16 + g;
    const int nkb = (seqlen + 63) >> 6;

    for (int kb = 0; kb < nkb; kb++) {
        __syncthreads();
        const int kbase = kb * 64;
        for (int i = tid; i < 64 * 32; i += 128) {
            int r = i >> 5, c4 = (i & 31) * 4;
            float4 kv = *(const float4*)(k + (size_t)(kbase + r) * D_MODEL + head * HEAD_DIM + c4);
            uint4 uk;
            uk.x = f2tf(kv.x); uk.y = f2tf(kv.y); uk.z = f2tf(kv.z); uk.w = f2tf(kv.w);
            *(uint4*)&Ks[r * KS_STR + c4] = uk;
            float4 vv = *(const float4*)(v + (size_t)(kbase + r) * D_MODEL + head * HEAD_DIM + c4);
            uint4 uv;
            uv.x = f2tf(vv.x); uv.y = f2tf(vv.y); uv.z = f2tf(vv.z); uv.w = f2tf(vv.w);
            *(uint4*)&Vs[r * VS_STR + c4] = uv;
        }
        __syncthreads();

        // S = Q @ K^T  (each warp: 16x64)
        float S[8][4];
        #pragma unroll
        for (int nj = 0; nj < 8; nj++)
            #pragma unroll
            for (int e = 0; e < 4; e++) S[nj][e] = 0.f;

        #pragma unroll
        for (int kk = 0; kk < 16; kk++) {
            uint32_t a[4];
            a[0] = Qs[rowA * QS_STR + kk * 8 + t];
            a[1] = Qs[(rowA + 8) * QS_STR + kk * 8 + t];
            a[2] = Qs[rowA * QS_STR + kk * 8 + t + 4];
            a[3] = Qs[(rowA + 8) * QS_STR + kk * 8 + t + 4];
            #pragma unroll
            for (int nj = 0; nj < 8; nj++) {
                uint32_t b[2];
                b[0] = Ks[(nj * 8 + g) * KS_STR + kk * 8 + t];
                b[1] = Ks[(nj * 8 + g) * KS_STR + kk * 8 + t + 4];
                mma_tf32(S[nj], a, b);
            }
        }

        // mask (only relevant for partial tiles)
        if (kbase + 64 > seqlen) {
            #pragma unroll
            for (int nj = 0; nj < 8; nj++) {
                int c0 = kbase + nj * 8 + t * 2;
                if (c0 >= seqlen)     { S[nj][0] = -1e30f; S[nj][2] = -1e30f; }
                if (c0 + 1 >= seqlen) { S[nj][1] = -1e30f; S[nj][3] = -1e30f; }
            }
        }

        // online softmax
        float mx0 = -INFINITY, mx1 = -INFINITY;
        #pragma unroll
        for (int nj = 0; nj < 8; nj++) {
            mx0 = fmaxf(mx0, fmaxf(S[nj][0], S[nj][1]));
            mx1 = fmaxf(mx1, fmaxf(S[nj][2], S[nj][3]));
        }
        #pragma unroll
        for (int off = 1; off <= 2; off <<= 1) {
            mx0 = fmaxf(mx0, __shfl_xor_sync(0xffffffffu, mx0, off));
            mx1 = fmaxf(mx1, __shfl_xor_sync(0xffffffffu, mx1, off));
        }
        const float mn0 = fmaxf(m0, mx0), mn1 = fmaxf(m1, mx1);
        const float corr0 = __expf(m0 - mn0), corr1 = __expf(m1 - mn1);
        m0 = mn0; m1 = mn1;

        float rs0 = 0.f, rs1 = 0.f;
        #pragma unroll
        for (int nj = 0; nj < 8; nj++) {
            float p0 = __expf(S[nj][0] - mn0);
            float p1 = __expf(S[nj][1] - mn0);
            float p2 = __expf(S[nj][2] - mn1);
            float p3 = __expf(S[nj][3] - mn1);
            rs0 += p0 + p1;
            rs1 += p2 + p3;
            Ps[rowA * PS_STR + nj * 8 + 2 * t]           = f2tf(p0);
            Ps[rowA * PS_STR + nj * 8 + 2 * t + 1]       = f2tf(p1);
            Ps[(rowA + 8) * PS_STR + nj * 8 + 2 * t]     = f2tf(p2);
            Ps[(rowA + 8) * PS_STR + nj * 8 + 2 * t + 1] = f2tf(p3);
        }
        #pragma unroll
        for (int off = 1; off <= 2; off <<= 1) {
            rs0 += __shfl_xor_sync(0xffffffffu, rs0, off);
            rs1 += __shfl_xor_sync(0xffffffffu, rs1, off);
        }
        l0 = l0 * corr0 + rs0;
        l1 = l1 * corr1 + rs1;
        #pragma unroll
        for (int nj = 0; nj < 16; nj++) {
            O[nj][0] *= corr0; O[nj][1] *= corr0;
            O[nj][2] *= corr1; O[nj][3] *= corr1;
        }
        __syncwarp();

        // O += P @ V
        #pragma unroll
        for (int kk = 0; kk < 8; kk++) {
            uint32_t a[4];
            a[0] = Ps[rowA * PS_STR + kk * 8 + t];
            a[1] = Ps[(rowA + 8) * PS_STR + kk * 8 + t];
            a[2] = Ps[rowA * PS_STR + kk * 8 + t + 4];
            a[3] = Ps[(rowA + 8) * PS_STR + kk * 8 + t + 4];
            #pragma unroll
            for (int nj = 0; nj < 16; nj++) {
                uint32_t b[2];
                b[0] = Vs[(kk * 8 + t) * VS_STR + nj * 8 + g];
                b[1] = Vs[(kk * 8 + t + 4) * VS_STR + nj * 8 + g];
                mma_tf32(O[nj], a, b);
            }
        }
    }

    const float inv0 = 1.f / l0, inv1 = 1.f / l1;
    #pragma unroll
    for (int nj = 0; nj < 16; nj++) {
        int gr = q0 + rowA;
        int col = head * HEAD_DIM + nj * 8 + t * 2;
        o[(size_t)gr * D_MODEL + col]           = O[nj][0] * inv0;
        o[(size_t)gr * D_MODEL + col + 1]       = O[nj][1] * inv0;
        o[(size_t)(gr + 8) * D_MODEL + col]     = O[nj][2] * inv1;
        o[(size_t)(gr + 8) * D_MODEL + col + 1] = O[nj][3] * inv1;
    }
}

// ============================================================================
// Launch
// ============================================================================
extern "C" void kernel_launch(void* const* d_in, const int* in_sizes, int n_in,
                              void* d_out, int out_size)
{
    (void)in_sizes; (void)n_in; (void)out_size;
    const float* x    = (const float*)d_in[0];
    const int* seqlen = (const int*)d_in[1];
    const int* gsizes = (const int*)d_in[2];
    const float* fcos = (const float*)d_in[3];
    const float* fsin = (const float*)d_in[4];
    const float* Wq = (const float*)d_in[5];
    const float* bq = (const float*)d_in[6];
    const float* Wk = (const float*)d_in[7];
    const float* bk = (const float*)d_in[8];
    const float* Wv = (const float*)d_in[9];
    const float* bv = (const float*)d_in[10];
    const float* Wo = (const float*)d_in[11];
    const float* bo = (const float*)d_in[12];
    const float* gq = (const float*)d_in[13];
    const float* gk = (const float*)d_in[14];
    float* out = (float*)d_out;

    float *pq, *pk, *pv, *patt;
    cudaGetSymbolAddress((void**)&pq, g_q);
    cudaGetSymbolAddress((void**)&pk, g_k);
    cudaGetSymbolAddress((void**)&pv, g_v);
    cudaGetSymbolAddress((void**)&patt, g_att);

    cudaFuncSetAttribute(flash_attn, cudaFuncAttributeMaxDynamicSharedMemorySize, FA_SMEM);

    dim3 ggrid(D_MODEL / 128, L_SEQ / 128);
    gemm_nt_bias<<<ggrid, 256>>>(x, Wq, bq, pq, L_SEQ, D_MODEL, D_MODEL);
    gemm_nt_bias<<<ggrid, 256>>>(x, Wk, bk, pk, L_SEQ, D_MODEL, D_MODEL);
    gemm_nt_bias<<<ggrid, 256>>>(x, Wv, bv, pv, L_SEQ, D_MODEL, D_MODEL);

    rmsnorm_rope<<<dim3(L_SEQ, 2), 256>>>(pq, pk, gq, gk, gsizes, fcos, fsin);

    flash_attn<<<dim3(L_SEQ / 64, N_HEADS), 128, FA_SMEM>>>(pq, pk, pv, patt, seqlen);

    gemm_nt_bias<<<ggrid, 256>>>(patt, Wo, bo, out, L_SEQ, D_MODEL, D_MODEL);
}

// round 6
// speedup vs baseline: 1.3650x; 1.3650x over previous
#include <cuda_runtime.h>
#include <cstdint>
#include <math.h>

#define L_SEQ 4096
#define D_MODEL 1536
#define N_HEADS 12
#define HEAD_DIM 128

// Scratch (device globals; allocation-free per harness rules)
__device__ float g_q[L_SEQ * D_MODEL];
__device__ float g_k[L_SEQ * D_MODEL];
__device__ float g_v[L_SEQ * D_MODEL];
__device__ float g_att[L_SEQ * D_MODEL];

// ===================== helpers =====================
__device__ __forceinline__ uint32_t f2tf(float f) {
    uint32_t u;
    asm("cvt.rna.tf32.f32 %0, %1;" : "=r"(u) : "f"(f));
    return u;
}

__device__ __forceinline__ uint32_t smem_u32(const void* p) {
    uint32_t a;
    asm("{ .reg .u64 t; cvta.to.shared.u64 t, %1; cvt.u32.u64 %0, t; }" : "=r"(a) : "l"(p));
    return a;
}

__device__ __forceinline__ void cp_async16(uint32_t dst, const void* src) {
    asm volatile("cp.async.cg.shared.global [%0], [%1], 16;" :: "r"(dst), "l"(src) : "memory");
}
#define CP_COMMIT() asm volatile("cp.async.commit_group;" ::: "memory")
#define CP_WAIT1()  asm volatile("cp.async.wait_group 1;" ::: "memory")
#define CP_WAIT0()  asm volatile("cp.async.wait_group 0;" ::: "memory")

__device__ __forceinline__ void mma_tf32(float* c, const uint32_t* a, const uint32_t* b) {
    asm volatile(
        "mma.sync.aligned.m16n8k8.row.col.f32.tf32.tf32.f32 "
        "{%0,%1,%2,%3}, {%4,%5,%6,%7}, {%8,%9}, {%0,%1,%2,%3};"
        : "+f"(c[0]), "+f"(c[1]), "+f"(c[2]), "+f"(c[3])
        : "r"(a[0]), "r"(a[1]), "r"(a[2]), "r"(a[3]), "r"(b[0]), "r"(b[1]));
}

// ============================================================================
// GEMM: C[z][M,N] = A[M,K] @ W[z][N,K]^T + b[z][N]   (tf32 mma, fp32 accum)
// 128x128x32 tiles, cp.async double-buffered raw-f32 smem, cvt at fragment.
// 256 threads, 8 warps (4x2), warp tile 32x64.
// smem: A[2][128][36] | B[2][128][36]  = 73728 B
// ============================================================================
#define GT 4608               // floats per k-tile buffer (128*36)
#define GEMM_SMEM (4 * GT * 4)

__global__ __launch_bounds__(256) void gemm_nt_bias(
    const float* __restrict__ A,
    const float* __restrict__ W0, const float* __restrict__ W1, const float* __restrict__ W2,
    const float* __restrict__ b0, const float* __restrict__ b1, const float* __restrict__ b2,
    float* __restrict__ C0, float* __restrict__ C1, float* __restrict__ C2)
{
    const int K = D_MODEL, Nn = D_MODEL;
    extern __shared__ __align__(16) float smf[];
    float* Asm = smf;            // [2][128][36]
    float* Bsm = smf + 2 * GT;   // [2][128][36]
    const uint32_t sA = smem_u32(Asm), sB = smem_u32(Bsm);

    const int tid = threadIdx.x;
    const int wid = tid >> 5, lane = tid & 31;
    const int g = lane >> 2, t = lane & 3;
    const int wm = wid >> 1, wn = wid & 1;
    const int bm = blockIdx.y * 128, bn = blockIdx.x * 128;

    const float* Bw; const float* bias; float* C;
    if (blockIdx.z == 0)      { Bw = W0; bias = b0; C = C0; }
    else if (blockIdx.z == 1) { Bw = W1; bias = b1; C = C1; }
    else                      { Bw = W2; bias = b2; C = C2; }

    float acc[2][8][4];
    #pragma unroll
    for (int mi = 0; mi < 2; mi++)
        #pragma unroll
        for (int nj = 0; nj < 8; nj++)
            #pragma unroll
            for (int e = 0; e < 4; e++) acc[mi][nj][e] = 0.f;

    const int lr = tid >> 3;         // 0..31
    const int lq = tid & 7;          // float4 slot in 32-float row
    const int nkt = K / 32;          // 48

    // prologue: issue k-tile 0
    #pragma unroll
    for (int j = 0; j < 4; j++) {
        int r = lr + j * 32;
        uint32_t doff = ((uint32_t)r * 36 + lq * 4) * 4;
        cp_async16(sA + doff, A  + (size_t)(bm + r) * K + lq * 4);
        cp_async16(sB + doff, Bw + (size_t)(bn + r) * K + lq * 4);
    }
    CP_COMMIT();

    for (int kt = 0; kt < nkt; kt++) {
        __syncthreads();   // everyone done reading the buffer we are about to overwrite
        if (kt + 1 < nkt) {
            const int b2f = (kt + 1) & 1;
            const float* Ap = A  + (size_t)bm * K + (kt + 1) * 32;
            const float* Bp = Bw + (size_t)bn * K + (kt + 1) * 32;
            #pragma unroll
            for (int j = 0; j < 4; j++) {
                int r = lr + j * 32;
                uint32_t doff = ((uint32_t)(b2f * GT) + (uint32_t)r * 36 + lq * 4) * 4;
                cp_async16(sA + doff, Ap + (size_t)r * K + lq * 4);
                cp_async16(sB + doff, Bp + (size_t)r * K + lq * 4);
            }
            CP_COMMIT();
            CP_WAIT1();
        } else {
            CP_WAIT0();
        }
        __syncthreads();

        const float* As = Asm + (kt & 1) * GT;
        const float* Bs = Bsm + (kt & 1) * GT;
        #pragma unroll
        for (int kk = 0; kk < 4; kk++) {
            uint32_t a[2][4], b[8][2];
            #pragma unroll
            for (int mi = 0; mi < 2; mi++) {
                int row = wm * 32 + mi * 16 + g;
                a[mi][0] = f2tf(As[row * 36 + kk * 8 + t]);
                a[mi][1] = f2tf(As[(row + 8) * 36 + kk * 8 + t]);
                a[mi][2] = f2tf(As[row * 36 + kk * 8 + t + 4]);
                a[mi][3] = f2tf(As[(row + 8) * 36 + kk * 8 + t + 4]);
            }
            #pragma unroll
            for (int nj = 0; nj < 8; nj++) {
                int col = wn * 64 + nj * 8 + g;
                b[nj][0] = f2tf(Bs[col * 36 + kk * 8 + t]);
                b[nj][1] = f2tf(Bs[col * 36 + kk * 8 + t + 4]);
            }
            #pragma unroll
            for (int mi = 0; mi < 2; mi++)
                #pragma unroll
                for (int nj = 0; nj < 8; nj++)
                    mma_tf32(acc[mi][nj], a[mi], b[nj]);
        }
    }

    #pragma unroll
    for (int mi = 0; mi < 2; mi++) {
        #pragma unroll
        for (int nj = 0; nj < 8; nj++) {
            int row = bm + wm * 32 + mi * 16 + g;
            int col = bn + wn * 64 + nj * 8 + t * 2;
            float bb0 = __ldg(bias + col), bb1 = __ldg(bias + col + 1);
            float2 o0 = make_float2(acc[mi][nj][0] + bb0, acc[mi][nj][1] + bb1);
            float2 o1 = make_float2(acc[mi][nj][2] + bb0, acc[mi][nj][3] + bb1);
            *(float2*)(C + (size_t)row * Nn + col)       = o0;
            *(float2*)(C + (size_t)(row + 8) * Nn + col) = o1;
        }
    }
}

// ============================================================================
// Fused RMS-norm (D=1536) + RoPE. grid = (L, 2): y==0 -> q, y==1 -> k.
// ============================================================================
__global__ __launch_bounds__(256) void rmsnorm_rope(
    const float* __restrict__ gq, const float* __restrict__ gk,
    const int* __restrict__ grid_sizes,
    const float* __restrict__ fcos, const float* __restrict__ fsin)
{
    const int row = blockIdx.x;
    const bool isK = (blockIdx.y != 0);
    float* p = (isK ? g_k : g_q) + (size_t)row * D_MODEL;
    const float* gam = isK ? gk : gq;

    float ss = 0.f;
    for (int i = threadIdx.x; i < D_MODEL; i += 256) {
        float v = p[i];
        ss += v * v;
    }
    __shared__ float red[8];
    #pragma unroll
    for (int o = 16; o; o >>= 1) ss += __shfl_xor_sync(0xffffffffu, ss, o);
    if ((threadIdx.x & 31) == 0) red[threadIdx.x >> 5] = ss;
    __syncthreads();
    __shared__ float s_rms;
    if (threadIdx.x == 0) {
        float tot = 0.f;
        #pragma unroll
        for (int i = 0; i < 8; i++) tot += red[i];
        s_rms = rsqrtf(tot / (float)D_MODEL + 1e-6f);
    }
    __syncthreads();
    const float rms = s_rms;

    const int f = grid_sizes[0], h = grid_sizes[1], w = grid_sizes[2];
    const int sl = f * h * w;
    if (row < sl) {
        const int fi = row / (h * w);
        const int rem = row % (h * w);
        const int hi = rem / w, wi = rem % w;
        for (int pp = threadIdx.x; pp < N_HEADS * 64; pp += 256) {
            const int head = pp >> 6;
            const int j = pp & 63;
            const int pos = (j < 22) ? fi : ((j < 43) ? hi : wi);
            const float co = fcos[pos * 64 + j];
            const float si = fsin[pos * 64 + j];
            const int ci = head * HEAD_DIM + 2 * j;
            const float xr = p[ci] * rms * gam[ci];
            const float xi = p[ci + 1] * rms * gam[ci + 1];
            p[ci]     = xr * co - xi * si;
            p[ci + 1] = xr * si + xi * co;
        }
    } else {
        for (int i = threadIdx.x; i < D_MODEL; i += 256) p[i] = p[i] * rms * gam[i];
    }
}

// ============================================================================
// Flash attention: BM=128 x BN=64, d=128, 8 warps (256 thr).
// K/V loaded raw f32 via single-buffered cp.async; cvt to tf32 at fragment load.
// smem words: Qs 128*132 (tf32) | Kr 64*132 f32 | Vr 64*136 f32 | Ps 128*68
// = 171 KB -> 1 CTA/SM.
// ============================================================================
#define QS_STR 132
#define KS_STR 132
#define VS_STR 136
#define PS_STR 68
#define FA_SMEM ((128 * QS_STR + 64 * KS_STR + 64 * VS_STR + 128 * PS_STR) * 4)

__global__ __launch_bounds__(256) void flash_attn(
    const float* __restrict__ q, const float* __restrict__ k,
    const float* __restrict__ v, float* __restrict__ o,
    const int* __restrict__ seq_lens)
{
    extern __shared__ uint32_t sm[];
    uint32_t* Qs = sm;                       // tf32
    float*    Kr = (float*)(sm + 128 * QS_STR);   // raw f32, stride 132
    float*    Vr = Kr + 64 * KS_STR;              // raw f32, stride 136
    uint32_t* Ps = (uint32_t*)(Vr + 64 * VS_STR);
    const uint32_t sK = smem_u32(Kr), sV = smem_u32(Vr);

    const int tid = threadIdx.x, wid = tid >> 5, lane = tid & 31;
    const int g = lane >> 2, t = lane & 3;
    const int q0 = blockIdx.x * 128;
    const int head = blockIdx.y;
    const int seqlen = seq_lens[0];
    const float scale = 0.08838834764831845f;  // 1/sqrt(128)
    const size_t kvcol = (size_t)head * HEAD_DIM;

    // K/V tile loader: 64 rows x 128 floats each. 256 threads:
    // each thread does 8 cp.async of 16B per array.
    const int lr = tid >> 2;                 // 0..63 (row)
    const int lq = tid & 3;                  // 0..3

    // prologue: issue K/V tile 0 while we convert Q
    {
        const float* kp = k + kvcol + (size_t)lr * D_MODEL;
        const float* vp = v + kvcol + (size_t)lr * D_MODEL;
        #pragma unroll
        for (int j = 0; j < 8; j++) {
            int c4 = (lq + j * 4) * 4;       // 0,16,..,124 spread across threads
            cp_async16(sK + ((uint32_t)lr * KS_STR + c4) * 4, kp + c4);
            cp_async16(sV + ((uint32_t)lr * VS_STR + c4) * 4, vp + c4);
        }
        CP_COMMIT();
    }

    // Load Q tile (cvt + fold softmax scale)
    for (int i = tid; i < 128 * 32; i += 256) {
        int r = i >> 5, c4 = (i & 31) * 4;
        float4 vq = *(const float4*)(q + (size_t)(q0 + r) * D_MODEL + kvcol + c4);
        uint4 u;
        u.x = f2tf(vq.x * scale); u.y = f2tf(vq.y * scale);
        u.z = f2tf(vq.z * scale); u.w = f2tf(vq.w * scale);
        *(uint4*)&Qs[r * QS_STR + c4] = u;
    }

    float m0 = -INFINITY, m1 = -INFINITY, l0 = 0.f, l1 = 0.f;
    float O[16][4];
    #pragma unroll
    for (int nj = 0; nj < 16; nj++)
        #pragma unroll
        for (int e = 0; e < 4; e++) O[nj][e] = 0.f;

    const int rowA = wid * 16 + g;
    const int nkb = (seqlen + 63) >> 6;

    for (int kb = 0; kb < nkb; kb++) {
        CP_WAIT0();
        __syncthreads();                      // K/V tile kb visible to all

        const int kbase = kb * 64;

        // S = Q @ K^T  (each warp: 16x64)
        float S[8][4];
        #pragma unroll
        for (int nj = 0; nj < 8; nj++)
            #pragma unroll
            for (int e = 0; e < 4; e++) S[nj][e] = 0.f;

        #pragma unroll
        for (int kk = 0; kk < 16; kk++) {
            uint32_t a[4];
            a[0] = Qs[rowA * QS_STR + kk * 8 + t];
            a[1] = Qs[(rowA + 8) * QS_STR + kk * 8 + t];
            a[2] = Qs[rowA * QS_STR + kk * 8 + t + 4];
            a[3] = Qs[(rowA + 8) * QS_STR + kk * 8 + t + 4];
            #pragma unroll
            for (int nj = 0; nj < 8; nj++) {
                uint32_t b[2];
                b[0] = f2tf(Kr[(nj * 8 + g) * KS_STR + kk * 8 + t]);
                b[1] = f2tf(Kr[(nj * 8 + g) * KS_STR + kk * 8 + t + 4]);
                mma_tf32(S[nj], a, b);
            }
        }

        if (kbase + 64 > seqlen) {
            #pragma unroll
            for (int nj = 0; nj < 8; nj++) {
                int c0 = kbase + nj * 8 + t * 2;
                if (c0 >= seqlen)     { S[nj][0] = -1e30f; S[nj][2] = -1e30f; }
                if (c0 + 1 >= seqlen) { S[nj][1] = -1e30f; S[nj][3] = -1e30f; }
            }
        }

        // online softmax
        float mx0 = -INFINITY, mx1 = -INFINITY;
        #pragma unroll
        for (int nj = 0; nj < 8; nj++) {
            mx0 = fmaxf(mx0, fmaxf(S[nj][0], S[nj][1]));
            mx1 = fmaxf(mx1, fmaxf(S[nj][2], S[nj][3]));
        }
        #pragma unroll
        for (int off = 1; off <= 2; off <<= 1) {
            mx0 = fmaxf(mx0, __shfl_xor_sync(0xffffffffu, mx0, off));
            mx1 = fmaxf(mx1, __shfl_xor_sync(0xffffffffu, mx1, off));
        }
        const float mn0 = fmaxf(m0, mx0), mn1 = fmaxf(m1, mx1);
        const float corr0 = __expf(m0 - mn0), corr1 = __expf(m1 - mn1);
        m0 = mn0; m1 = mn1;

        float rs0 = 0.f, rs1 = 0.f;
        #pragma unroll
        for (int nj = 0; nj < 8; nj++) {
            float p0 = __expf(S[nj][0] - mn0);
            float p1 = __expf(S[nj][1] - mn0);
            float p2 = __expf(S[nj][2] - mn1);
            float p3 = __expf(S[nj][3] - mn1);
            rs0 += p0 + p1;
            rs1 += p2 + p3;
            uint2 u0 = make_uint2(f2tf(p0), f2tf(p1));
            uint2 u1 = make_uint2(f2tf(p2), f2tf(p3));
            *(uint2*)&Ps[rowA * PS_STR + nj * 8 + 2 * t]       = u0;
            *(uint2*)&Ps[(rowA + 8) * PS_STR + nj * 8 + 2 * t] = u1;
        }
        #pragma unroll
        for (int off = 1; off <= 2; off <<= 1) {
            rs0 += __shfl_xor_sync(0xffffffffu, rs0, off);
            rs1 += __shfl_xor_sync(0xffffffffu, rs1, off);
        }
        l0 = l0 * corr0 + rs0;
        l1 = l1 * corr1 + rs1;
        #pragma unroll
        for (int nj = 0; nj < 16; nj++) {
            O[nj][0] *= corr0; O[nj][1] *= corr0;
            O[nj][2] *= corr1; O[nj][3] *= corr1;
        }
        __syncwarp();

        // O += P @ V
        #pragma unroll
        for (int kk = 0; kk < 8; kk++) {
            uint32_t a[4];
            a[0] = Ps[rowA * PS_STR + kk * 8 + t];
            a[1] = Ps[(rowA + 8) * PS_STR + kk * 8 + t];
            a[2] = Ps[rowA * PS_STR + kk * 8 + t + 4];
            a[3] = Ps[(rowA + 8) * PS_STR + kk * 8 + t + 4];
            #pragma unroll
            for (int nj = 0; nj < 16; nj++) {
                uint32_t b[2];
                b[0] = f2tf(Vr[(kk * 8 + t) * VS_STR + nj * 8 + g]);
                b[1] = f2tf(Vr[(kk * 8 + t + 4) * VS_STR + nj * 8 + g]);
                mma_tf32(O[nj], a, b);
            }
        }

        // issue next K/V tile (overwrites current buffers only after all
        // warps are done reading them)
        __syncthreads();
        if (kb + 1 < nkb) {
            const float* kp = k + (size_t)(kb + 1) * 64 * D_MODEL + kvcol + (size_t)lr * D_MODEL;
            const float* vp = v + (size_t)(kb + 1) * 64 * D_MODEL + kvcol + (size_t)lr * D_MODEL;
            #pragma unroll
            for (int j = 0; j < 8; j++) {
                int c4 = (lq + j * 4) * 4;
                cp_async16(sK + ((uint32_t)lr * KS_STR + c4) * 4, kp + c4);
                cp_async16(sV + ((uint32_t)lr * VS_STR + c4) * 4, vp + c4);
            }
            CP_COMMIT();
        }
    }

    const float inv0 = 1.f / l0, inv1 = 1.f / l1;
    #pragma unroll
    for (int nj = 0; nj < 16; nj++) {
        int gr = q0 + rowA;
        int col = head * HEAD_DIM + nj * 8 + t * 2;
        float2 o0 = make_float2(O[nj][0] * inv0, O[nj][1] * inv0);
        float2 o1 = make_float2(O[nj][2] * inv1, O[nj][3] * inv1);
        *(float2*)(o + (size_t)gr * D_MODEL + col)       = o0;
        *(float2*)(o + (size_t)(gr + 8) * D_MODEL + col) = o1;
    }
}

// ============================================================================
// Launch
// ============================================================================
extern "C" void kernel_launch(void* const* d_in, const int* in_sizes, int n_in,
                              void* d_out, int out_size)
{
    (void)in_sizes; (void)n_in; (void)out_size;
    const float* x    = (const float*)d_in[0];
    const int* seqlen = (const int*)d_in[1];
    const int* gsizes = (const int*)d_in[2];
    const float* fcos = (const float*)d_in[3];
    const float* fsin = (const float*)d_in[4];
    const float* Wq = (const float*)d_in[5];
    const float* bq = (const float*)d_in[6];
    const float* Wk = (const float*)d_in[7];
    const float* bk = (const float*)d_in[8];
    const float* Wv = (const float*)d_in[9];
    const float* bv = (const float*)d_in[10];
    const float* Wo = (const float*)d_in[11];
    const float* bo = (const float*)d_in[12];
    const float* gq = (const float*)d_in[13];
    const float* gk = (const float*)d_in[14];
    float* out = (float*)d_out;

    float *pq, *pk, *pv, *patt;
    cudaGetSymbolAddress((void**)&pq, g_q);
    cudaGetSymbolAddress((void**)&pk, g_k);
    cudaGetSymbolAddress((void**)&pv, g_v);
    cudaGetSymbolAddress((void**)&patt, g_att);

    cudaFuncSetAttribute(gemm_nt_bias, cudaFuncAttributeMaxDynamicSharedMemorySize, GEMM_SMEM);
    cudaFuncSetAttribute(flash_attn, cudaFuncAttributeMaxDynamicSharedMemorySize, FA_SMEM);

    // Fused QKV projection: grid.z selects weight/out
    gemm_nt_bias<<<dim3(D_MODEL / 128, L_SEQ / 128, 3), 256, GEMM_SMEM>>>(
        x, Wq, Wk, Wv, bq, bk, bv, pq, pk, pv);

    rmsnorm_rope<<<dim3(L_SEQ, 2), 256>>>(gq, gk, gsizes, fcos, fsin);

    flash_attn<<<dim3(L_SEQ / 128, N_HEADS), 256, FA_SMEM>>>(pq, pk, pv, patt, seqlen);

    gemm_nt_bias<<<dim3(D_MODEL / 128, L_SEQ / 128, 1), 256, GEMM_SMEM>>>(
        patt, Wo, Wo, Wo, bo, bo, bo, out, out, out);
}

// round 9
// speedup vs baseline: 1.4317x; 1.0488x over previous
#include <cuda_runtime.h>
#include <cstdint>
#include <math.h>

#define L_SEQ 4096
#define D_MODEL 1536
#define N_HEADS 12
#define HEAD_DIM 128
#define QK_SCALE 0.08838834764831845f   // 1/sqrt(128)

// Scratch (device globals; allocation-free per harness rules)
__device__ float g_q[L_SEQ * D_MODEL];
__device__ float g_k[L_SEQ * D_MODEL];
__device__ float g_v[L_SEQ * D_MODEL];
__device__ float g_att[L_SEQ * D_MODEL];
__device__ float g_x [L_SEQ * D_MODEL];          // tf32-rounded x
__device__ float g_wq[D_MODEL * D_MODEL];        // tf32-rounded weights
__device__ float g_wk[D_MODEL * D_MODEL];
__device__ float g_wv[D_MODEL * D_MODEL];
__device__ float g_wo[D_MODEL * D_MODEL];

// ===================== helpers =====================
__device__ __forceinline__ uint32_t f2tf(float f) {
    uint32_t u;
    asm("cvt.rna.tf32.f32 %0, %1;" : "=r"(u) : "f"(f));
    return u;
}
__device__ __forceinline__ float f2tff(float f) { return __uint_as_float(f2tf(f)); }

__device__ __forceinline__ uint32_t smem_u32(const void* p) {
    uint32_t a;
    asm("{ .reg .u64 t; cvta.to.shared.u64 t, %1; cvt.u32.u64 %0, t; }" : "=r"(a) : "l"(p));
    return a;
}

__device__ __forceinline__ void cp_async16(uint32_t dst, const void* src) {
    asm volatile("cp.async.cg.shared.global [%0], [%1], 16;" :: "r"(dst), "l"(src) : "memory");
}
#define CP_COMMIT() asm volatile("cp.async.commit_group;" ::: "memory")
#define CP_WAIT1()  asm volatile("cp.async.wait_group 1;" ::: "memory")
#define CP_WAIT0()  asm volatile("cp.async.wait_group 0;" ::: "memory")

__device__ __forceinline__ void mma_tf32(float* c, const uint32_t* a, const uint32_t* b) {
    asm volatile(
        "mma.sync.aligned.m16n8k8.row.col.f32.tf32.tf32.f32 "
        "{%0,%1,%2,%3}, {%4,%5,%6,%7}, {%8,%9}, {%0,%1,%2,%3};"
        : "+f"(c[0]), "+f"(c[1]), "+f"(c[2]), "+f"(c[3])
        : "r"(a[0]), "r"(a[1]), "r"(a[2]), "r"(a[3]), "r"(b[0]), "r"(b[1]));
}

// ============================================================================
// tf32 round-copy (x, weights)
// ============================================================================
__global__ __launch_bounds__(256) void round_copy(const float* __restrict__ s,
                                                  float* __restrict__ d, int n4)
{
    int i = blockIdx.x * 256 + threadIdx.x;
    if (i < n4) {
        float4 v = ((const float4*)s)[i];
        v.x = f2tff(v.x); v.y = f2tff(v.y); v.z = f2tff(v.z); v.w = f2tff(v.w);
        ((float4*)d)[i] = v;
    }
}

// ============================================================================
// GEMM: C[z][M,N] = A[M,K] @ W[z][N,K]^T + b[z][N]
// Inputs pre-rounded to tf32 -> no cvt in mainloop.
// 128x128x32 tiles, cp.async double-buffered, 256 threads (8 warps 4x2).
// ============================================================================
#define GT 4608               // floats per k-tile buffer (128*36)
#define GEMM_SMEM (4 * GT * 4)

__global__ __launch_bounds__(256) void gemm_nt_bias(
    const float* __restrict__ A,
    const float* __restrict__ W0, const float* __restrict__ W1, const float* __restrict__ W2,
    const float* __restrict__ b0, const float* __restrict__ b1, const float* __restrict__ b2,
    float* __restrict__ C0, float* __restrict__ C1, float* __restrict__ C2,
    int round_out_z)
{
    const int K = D_MODEL, Nn = D_MODEL;
    extern __shared__ __align__(16) float smf[];
    float* Asm = smf;            // [2][128][36]
    float* Bsm = smf + 2 * GT;   // [2][128][36]
    const uint32_t sA = smem_u32(Asm), sB = smem_u32(Bsm);

    const int tid = threadIdx.x;
    const int wid = tid >> 5, lane = tid & 31;
    const int g = lane >> 2, t = lane & 3;
    const int wm = wid >> 1, wn = wid & 1;
    const int bm = blockIdx.y * 128, bn = blockIdx.x * 128;

    const float* Bw; const float* bias; float* C;
    if (blockIdx.z == 0)      { Bw = W0; bias = b0; C = C0; }
    else if (blockIdx.z == 1) { Bw = W1; bias = b1; C = C1; }
    else                      { Bw = W2; bias = b2; C = C2; }
    const bool rnd = ((int)blockIdx.z == round_out_z);

    float acc[2][8][4];
    #pragma unroll
    for (int mi = 0; mi < 2; mi++)
        #pragma unroll
        for (int nj = 0; nj < 8; nj++)
            #pragma unroll
            for (int e = 0; e < 4; e++) acc[mi][nj][e] = 0.f;

    const int lr = tid >> 3;         // 0..31
    const int lq = tid & 7;          // float4 slot in 32-float row
    const int nkt = K / 32;          // 48

    // prologue: issue k-tile 0
    #pragma unroll
    for (int j = 0; j < 4; j++) {
        int r = lr + j * 32;
        uint32_t doff = ((uint32_t)r * 36 + lq * 4) * 4;
        cp_async16(sA + doff, A  + (size_t)(bm + r) * K + lq * 4);
        cp_async16(sB + doff, Bw + (size_t)(bn + r) * K + lq * 4);
    }
    CP_COMMIT();

    for (int kt = 0; kt < nkt; kt++) {
        __syncthreads();
        if (kt + 1 < nkt) {
            const int b2f = (kt + 1) & 1;
            const float* Ap = A  + (size_t)bm * K + (kt + 1) * 32;
            const float* Bp = Bw + (size_t)bn * K + (kt + 1) * 32;
            #pragma unroll
            for (int j = 0; j < 4; j++) {
                int r = lr + j * 32;
                uint32_t doff = ((uint32_t)(b2f * GT) + (uint32_t)r * 36 + lq * 4) * 4;
                cp_async16(sA + doff, Ap + (size_t)r * K + lq * 4);
                cp_async16(sB + doff, Bp + (size_t)r * K + lq * 4);
            }
            CP_COMMIT();
            CP_WAIT1();
        } else {
            CP_WAIT0();
        }
        __syncthreads();

        const float* As = Asm + (kt & 1) * GT;
        const float* Bs = Bsm + (kt & 1) * GT;
        #pragma unroll
        for (int kk = 0; kk < 4; kk++) {
            uint32_t a[2][4], b[8][2];
            #pragma unroll
            for (int mi = 0; mi < 2; mi++) {
                int row = wm * 32 + mi * 16 + g;
                a[mi][0] = __float_as_uint(As[row * 36 + kk * 8 + t]);
                a[mi][1] = __float_as_uint(As[(row + 8) * 36 + kk * 8 + t]);
                a[mi][2] = __float_as_uint(As[row * 36 + kk * 8 + t + 4]);
                a[mi][3] = __float_as_uint(As[(row + 8) * 36 + kk * 8 + t + 4]);
            }
            #pragma unroll
            for (int nj = 0; nj < 8; nj++) {
                int col = wn * 64 + nj * 8 + g;
                b[nj][0] = __float_as_uint(Bs[col * 36 + kk * 8 + t]);
                b[nj][1] = __float_as_uint(Bs[col * 36 + kk * 8 + t + 4]);
            }
            #pragma unroll
            for (int mi = 0; mi < 2; mi++)
                #pragma unroll
                for (int nj = 0; nj < 8; nj++)
                    mma_tf32(acc[mi][nj], a[mi], b[nj]);
        }
    }

    #pragma unroll
    for (int mi = 0; mi < 2; mi++) {
        #pragma unroll
        for (int nj = 0; nj < 8; nj++) {
            int row = bm + wm * 32 + mi * 16 + g;
            int col = bn + wn * 64 + nj * 8 + t * 2;
            float bb0 = __ldg(bias + col), bb1 = __ldg(bias + col + 1);
            float e0 = acc[mi][nj][0] + bb0, e1 = acc[mi][nj][1] + bb1;
            float e2 = acc[mi][nj][2] + bb0, e3 = acc[mi][nj][3] + bb1;
            if (rnd) { e0 = f2tff(e0); e1 = f2tff(e1); e2 = f2tff(e2); e3 = f2tff(e3); }
            *(float2*)(C + (size_t)row * Nn + col)       = make_float2(e0, e1);
            *(float2*)(C + (size_t)(row + 8) * Nn + col) = make_float2(e2, e3);
        }
    }
}

// ============================================================================
// Fused RMS-norm (D=1536) + RoPE. grid = (L, 2): y==0 -> q, y==1 -> k.
// Writes tf32-rounded output; q additionally pre-scaled by 1/sqrt(d).
// ============================================================================
__global__ __launch_bounds__(256) void rmsnorm_rope(
    const float* __restrict__ gq, const float* __restrict__ gk,
    const int* __restrict__ grid_sizes,
    const float* __restrict__ fcos, const float* __restrict__ fsin)
{
    const int row = blockIdx.x;
    const bool isK = (blockIdx.y != 0);
    float* p = (isK ? g_k : g_q) + (size_t)row * D_MODEL;
    const float* gam = isK ? gk : gq;
    const float post = isK ? 1.0f : QK_SCALE;

    float ss = 0.f;
    for (int i = threadIdx.x; i < D_MODEL; i += 256) {
        float v = p[i];
        ss += v * v;
    }
    __shared__ float red[8];
    #pragma unroll
    for (int o = 16; o; o >>= 1) ss += __shfl_xor_sync(0xffffffffu, ss, o);
    if ((threadIdx.x & 31) == 0) red[threadIdx.x >> 5] = ss;
    __syncthreads();
    __shared__ float s_rms;
    if (threadIdx.x == 0) {
        float tot = 0.f;
        #pragma unroll
        for (int i = 0; i < 8; i++) tot += red[i];
        s_rms = rsqrtf(tot / (float)D_MODEL + 1e-6f);
    }
    __syncthreads();
    const float rms = s_rms;

    const int f = grid_sizes[0], h = grid_sizes[1], w = grid_sizes[2];
    const int sl = f * h * w;
    if (row < sl) {
        const int fi = row / (h * w);
        const int rem = row % (h * w);
        const int hi = rem / w, wi = rem % w;
        for (int pp = threadIdx.x; pp < N_HEADS * 64; pp += 256) {
            const int head = pp >> 6;
            const int j = pp & 63;
            const int pos = (j < 22) ? fi : ((j < 43) ? hi : wi);
            const float co = fcos[pos * 64 + j];
            const float si = fsin[pos * 64 + j];
            const int ci = head * HEAD_DIM + 2 * j;
            const float xr = p[ci] * rms * gam[ci];
            const float xi = p[ci + 1] * rms * gam[ci + 1];
            p[ci]     = f2tff((xr * co - xi * si) * post);
            p[ci + 1] = f2tff((xr * si + xi * co) * post);
        }
    } else {
        for (int i = threadIdx.x; i < D_MODEL; i += 256)
            p[i] = f2tff(p[i] * rms * gam[i] * post);
    }
}

// ============================================================================
// Flash attention: BM=128 x BN=64, d=128, 8 warps (256 thr).
// Q fragments in registers (one-time smem staging). K/V double-buffered
// cp.async (raw pre-rounded tf32 bits -> no cvt). P via smem.
// smem words: K[2]*8448 | V[2]*8448 | Ps 8704 = 42496 words (166 KB).
// ============================================================================
#define KVSTR 132
#define PS_STR 68
#define FA_SMEM (42496 * 4)

__global__ __launch_bounds__(256) void flash_attn(
    const float* __restrict__ q, const float* __restrict__ k,
    const float* __restrict__ v, float* __restrict__ o,
    const int* __restrict__ seq_lens)
{
    extern __shared__ uint32_t sm[];
    float*    KV = (float*)sm;           // K0:0  K1:8448  V0:16896  V1:25344
    uint32_t* Ps = sm + 33792;
    const uint32_t sKV = smem_u32(KV);

    const int tid = threadIdx.x, wid = tid >> 5, lane = tid & 31;
    const int g = lane >> 2, t = lane & 3;
    const int q0 = blockIdx.x * 128;
    const int head = blockIdx.y;
    const int seqlen = seq_lens[0];
    const size_t kvcol = (size_t)head * HEAD_DIM;
    const int rowA = wid * 16 + g;

    // ---- stage Q tile (already rounded+scaled) and grab fragments ----
    for (int i = tid; i < 128 * 32; i += 256) {
        int r = i >> 5, c4 = (i & 31) * 4;
        *(float4*)(KV + r * KVSTR + c4) =
            *(const float4*)(q + (size_t)(q0 + r) * D_MODEL + kvcol + c4);
    }
    __syncthreads();
    uint32_t Qa[16][4];
    #pragma unroll
    for (int kk = 0; kk < 16; kk++) {
        Qa[kk][0] = __float_as_uint(KV[rowA * KVSTR + kk * 8 + t]);
        Qa[kk][1] = __float_as_uint(KV[(rowA + 8) * KVSTR + kk * 8 + t]);
        Qa[kk][2] = __float_as_uint(KV[rowA * KVSTR + kk * 8 + t + 4]);
        Qa[kk][3] = __float_as_uint(KV[(rowA + 8) * KVSTR + kk * 8 + t + 4]);
    }
    __syncthreads();

    // ---- K/V tile loader ----
    const int lr = tid >> 2, lq = tid & 3;
    const int nkb = (seqlen + 63) >> 6;
    auto issue_kv = [&](int kb) {
        const float* kp = k + (size_t)kb * 64 * D_MODEL + kvcol + (size_t)lr * D_MODEL;
        const float* vp = v + (size_t)kb * 64 * D_MODEL + kvcol + (size_t)lr * D_MODEL;
        const uint32_t kb_s = sKV + (uint32_t)(((kb & 1) * 8448 + lr * KVSTR) * 4);
        const uint32_t vb_s = sKV + (uint32_t)(((16896 + (kb & 1) * 8448) + lr * KVSTR) * 4);
        #pragma unroll
        for (int j = 0; j < 8; j++) {
            int c4 = (lq + j * 4) * 4;
            cp_async16(kb_s + c4 * 4, kp + c4);
            cp_async16(vb_s + c4 * 4, vp + c4);
        }
        CP_COMMIT();
    };
    issue_kv(0);
    if (nkb > 1) issue_kv(1);

    float m0 = -INFINITY, m1 = -INFINITY, l0 = 0.f, l1 = 0.f;
    float O[16][4];
    #pragma unroll
    for (int nj = 0; nj < 16; nj++)
        #pragma unroll
        for (int e = 0; e < 4; e++) O[nj][e] = 0.f;

    for (int kb = 0; kb < nkb; kb++) {
        if (kb + 1 < nkb) CP_WAIT1(); else CP_WAIT0();
        __syncthreads();                      // K/V tile kb visible to all

        const float* Kb = KV + (kb & 1) * 8448;
        const float* Vb = KV + 16896 + (kb & 1) * 8448;
        const int kbase = kb * 64;

        // S = Q @ K^T  (each warp: 16x64)
        float S[8][4];
        #pragma unroll
        for (int nj = 0; nj < 8; nj++)
            #pragma unroll
            for (int e = 0; e < 4; e++) S[nj][e] = 0.f;

        #pragma unroll
        for (int kk = 0; kk < 16; kk++) {
            #pragma unroll
            for (int nj = 0; nj < 8; nj++) {
                uint32_t b[2];
                b[0] = __float_as_uint(Kb[(nj * 8 + g) * KVSTR + kk * 8 + t]);
                b[1] = __float_as_uint(Kb[(nj * 8 + g) * KVSTR + kk * 8 + t + 4]);
                mma_tf32(S[nj], Qa[kk], b);
            }
        }

        if (kbase + 64 > seqlen) {
            #pragma unroll
            for (int nj = 0; nj < 8; nj++) {
                int c0 = kbase + nj * 8 + t * 2;
                if (c0 >= seqlen)     { S[nj][0] = -1e30f; S[nj][2] = -1e30f; }
                if (c0 + 1 >= seqlen) { S[nj][1] = -1e30f; S[nj][3] = -1e30f; }
            }
        }

        // online softmax
        float mx0 = -INFINITY, mx1 = -INFINITY;
        #pragma unroll
        for (int nj = 0; nj < 8; nj++) {
            mx0 = fmaxf(mx0, fmaxf(S[nj][0], S[nj][1]));
            mx1 = fmaxf(mx1, fmaxf(S[nj][2], S[nj][3]));
        }
        #pragma unroll
        for (int off = 1; off <= 2; off <<= 1) {
            mx0 = fmaxf(mx0, __shfl_xor_sync(0xffffffffu, mx0, off));
            mx1 = fmaxf(mx1, __shfl_xor_sync(0xffffffffu, mx1, off));
        }
        const float mn0 = fmaxf(m0, mx0), mn1 = fmaxf(m1, mx1);
        const float corr0 = __expf(m0 - mn0), corr1 = __expf(m1 - mn1);
        m0 = mn0; m1 = mn1;

        float rs0 = 0.f, rs1 = 0.f;
        #pragma unroll
        for (int nj = 0; nj < 8; nj++) {
            float p0 = __expf(S[nj][0] - mn0);
            float p1 = __expf(S[nj][1] - mn0);
            float p2 = __expf(S[nj][2] - mn1);
            float p3 = __expf(S[nj][3] - mn1);
            rs0 += p0 + p1;
            rs1 += p2 + p3;
            uint2 u0 = make_uint2(f2tf(p0), f2tf(p1));
            uint2 u1 = make_uint2(f2tf(p2), f2tf(p3));
            *(uint2*)&Ps[rowA * PS_STR + nj * 8 + 2 * t]       = u0;
            *(uint2*)&Ps[(rowA + 8) * PS_STR + nj * 8 + 2 * t] = u1;
        }
        #pragma unroll
        for (int off = 1; off <= 2; off <<= 1) {
            rs0 += __shfl_xor_sync(0xffffffffu, rs0, off);
            rs1 += __shfl_xor_sync(0xffffffffu, rs1, off);
        }
        l0 = l0 * corr0 + rs0;
        l1 = l1 * corr1 + rs1;
        #pragma unroll
        for (int nj = 0; nj < 16; nj++) {
            O[nj][0] *= corr0; O[nj][1] *= corr0;
            O[nj][2] *= corr1; O[nj][3] *= corr1;
        }
        __syncwarp();

        // O += P @ V
        #pragma unroll
        for (int kk = 0; kk < 8; kk++) {
            uint32_t a[4];
            a[0] = Ps[rowA * PS_STR + kk * 8 + t];
            a[1] = Ps[(rowA + 8) * PS_STR + kk * 8 + t];
            a[2] = Ps[rowA * PS_STR + kk * 8 + t + 4];
            a[3] = Ps[(rowA + 8) * PS_STR + kk * 8 + t + 4];
            #pragma unroll
            for (int nj = 0; nj < 16; nj++) {
                uint32_t b[2];
                b[0] = __float_as_uint(Vb[(kk * 8 + t) * KVSTR + nj * 8 + g]);
                b[1] = __float_as_uint(Vb[(kk * 8 + t + 4) * KVSTR + nj * 8 + g]);
                mma_tf32(O[nj], a, b);
            }
        }

        // all warps done with buffer (kb&1) -> refill it with tile kb+2
        __syncthreads();
        if (kb + 2 < nkb) issue_kv(kb + 2);
    }

    // epilogue: write tf32-rounded (consumed by Wo GEMM)
    const float inv0 = 1.f / l0, inv1 = 1.f / l1;
    #pragma unroll
    for (int nj = 0; nj < 16; nj++) {
        int gr = q0 + rowA;
        int col = head * HEAD_DIM + nj * 8 + t * 2;
        float2 o0 = make_float2(f2tff(O[nj][0] * inv0), f2tff(O[nj][1] * inv0));
        float2 o1 = make_float2(f2tff(O[nj][2] * inv1), f2tff(O[nj][3] * inv1));
        *(float2*)(o + (size_t)gr * D_MODEL + col)       = o0;
        *(float2*)(o + (size_t)(gr + 8) * D_MODEL + col) = o1;
    }
}

// ============================================================================
// Launch
// ============================================================================
extern "C" void kernel_launch(void* const* d_in, const int* in_sizes, int n_in,
                              void* d_out, int out_size)
{
    (void)in_sizes; (void)n_in; (void)out_size;
    const float* x    = (const float*)d_in[0];
    const int* seqlen = (const int*)d_in[1];
    const int* gsizes = (const int*)d_in[2];
    const float* fcos = (const float*)d_in[3];
    const float* fsin = (const float*)d_in[4];
    const float* Wq = (const float*)d_in[5];
    const float* bq = (const float*)d_in[6];
    const float* Wk = (const float*)d_in[7];
    const float* bk = (const float*)d_in[8];
    const float* Wv = (const float*)d_in[9];
    const float* bv = (const float*)d_in[10];
    const float* Wo = (const float*)d_in[11];
    const float* bo = (const float*)d_in[12];
    const float* gq = (const float*)d_in[13];
    const float* gk = (const float*)d_in[14];
    float* out = (float*)d_out;

    float *pq, *pk, *pv, *patt, *px, *pwq, *pwk, *pwv, *pwo;
    cudaGetSymbolAddress((void**)&pq,  g_q);
    cudaGetSymbolAddress((void**)&pk,  g_k);
    cudaGetSymbolAddress((void**)&pv,  g_v);
    cudaGetSymbolAddress((void**)&patt, g_att);
    cudaGetSymbolAddress((void**)&px,  g_x);
    cudaGetSymbolAddress((void**)&pwq, g_wq);
    cudaGetSymbolAddress((void**)&pwk, g_wk);
    cudaGetSymbolAddress((void**)&pwv, g_wv);
    cudaGetSymbolAddress((void**)&pwo, g_wo);

    cudaFuncSetAttribute(gemm_nt_bias, cudaFuncAttributeMaxDynamicSharedMemorySize, GEMM_SMEM);
    cudaFuncSetAttribute(flash_attn, cudaFuncAttributeMaxDynamicSharedMemorySize, FA_SMEM);

    // pre-round inputs to tf32 (bit-identical to rounding at consume time)
    const int nx4 = L_SEQ * D_MODEL / 4, nw4 = D_MODEL * D_MODEL / 4;
    round_copy<<<(nx4 + 255) / 256, 256>>>(x,  px,  nx4);
    round_copy<<<(nw4 + 255) / 256, 256>>>(Wq, pwq, nw4);
    round_copy<<<(nw4 + 255) / 256, 256>>>(Wk, pwk, nw4);
    round_copy<<<(nw4 + 255) / 256, 256>>>(Wv, pwv, nw4);
    round_copy<<<(nw4 + 255) / 256, 256>>>(Wo, pwo, nw4);

    // Fused QKV projection: grid.z selects weight/out; V output rounded
    gemm_nt_bias<<<dim3(D_MODEL / 128, L_SEQ / 128, 3), 256, GEMM_SMEM>>>(
        px, pwq, pwk, pwv, bq, bk, bv, pq, pk, pv, 2);

    rmsnorm_rope<<<dim3(L_SEQ, 2), 256>>>(gq, gk, gsizes, fcos, fsin);

    flash_attn<<<dim3(L_SEQ / 128, N_HEADS), 256, FA_SMEM>>>(pq, pk, pv, patt, seqlen);

    gemm_nt_bias<<<dim3(D_MODEL / 128, L_SEQ / 128, 1), 256, GEMM_SMEM>>>(
        patt, pwo, pwo, pwo, bo, bo, bo, out, out, out, -1);
}

// round 14
// speedup vs baseline: 2.3814x; 1.6633x over previous
#include <cuda_runtime.h>
#include <cuda_fp16.h>
#include <cstdint>
#include <math.h>

#define L_SEQ 4096
#define D_MODEL 1536
#define N_HEADS 12
#define HEAD_DIM 128
#define QK_SCALE 0.08838834764831845f   // 1/sqrt(128)

// Scratch (device globals; allocation-free per harness rules)
__device__ float  g_q [L_SEQ * D_MODEL];          // fp32 GEMM outputs
__device__ float  g_k [L_SEQ * D_MODEL];
__device__ float  g_v [L_SEQ * D_MODEL];
__device__ __half g_xh[L_SEQ * D_MODEL];          // half x
__device__ __half g_qh[L_SEQ * D_MODEL];          // half q (rms+rope+scale)
__device__ __half g_kh[L_SEQ * D_MODEL];          // half k (rms+rope)
__device__ __half g_vt[L_SEQ * D_MODEL];          // half V transposed [head][dim][seq]
__device__ __half g_ah[L_SEQ * D_MODEL];          // half attention output
__device__ __half g_wqh[D_MODEL * D_MODEL];
__device__ __half g_wkh[D_MODEL * D_MODEL];
__device__ __half g_wvh[D_MODEL * D_MODEL];
__device__ __half g_woh[D_MODEL * D_MODEL];

// ===================== helpers =====================
__device__ __forceinline__ uint32_t smem_u32(const void* p) {
    uint32_t a;
    asm("{ .reg .u64 t; cvta.to.shared.u64 t, %1; cvt.u32.u64 %0, t; }" : "=r"(a) : "l"(p));
    return a;
}

__device__ __forceinline__ void cp_async16(uint32_t dst, const void* src) {
    asm volatile("cp.async.cg.shared.global [%0], [%1], 16;" :: "r"(dst), "l"(src) : "memory");
}
#define CP_COMMIT() asm volatile("cp.async.commit_group;" ::: "memory")
#define CP_WAIT1()  asm volatile("cp.async.wait_group 1;" ::: "memory")
#define CP_WAIT0()  asm volatile("cp.async.wait_group 0;" ::: "memory")

// fp16 mma, fp32 accumulate
__device__ __forceinline__ void mma_f16(float* c, const uint32_t* a, uint32_t b0, uint32_t b1) {
    asm volatile(
        "mma.sync.aligned.m16n8k16.row.col.f32.f16.f16.f32 "
        "{%0,%1,%2,%3}, {%4,%5,%6,%7}, {%8,%9}, {%0,%1,%2,%3};"
        : "+f"(c[0]), "+f"(c[1]), "+f"(c[2]), "+f"(c[3])
        : "r"(a[0]), "r"(a[1]), "r"(a[2]), "r"(a[3]), "r"(b0), "r"(b1));
}

__device__ __forceinline__ uint32_t h2u(__half2 h) { return *(uint32_t*)&h; }

// ============================================================================
// fp32 -> half convert
// ============================================================================
__global__ __launch_bounds__(256) void cvt_half(const float* __restrict__ s,
                                                __half* __restrict__ d, int n4)
{
    int i = blockIdx.x * 256 + threadIdx.x;
    if (i < n4) {
        float4 v = ((const float4*)s)[i];
        ((__half2*)d)[2 * i]     = __floats2half2_rn(v.x, v.y);
        ((__half2*)d)[2 * i + 1] = __floats2half2_rn(v.z, v.w);
    }
}

// ============================================================================
// fp16 GEMM: C[z][M,N] = A[M,K] @ W[z][N,K]^T + b[z][N]  (f32 accum)
// 128x128 tiles, k-tile = 64 halves (128B rows), 2-stage cp.async pipeline.
// 256 threads, 8 warps (4x2), warp tile 32x64, m16n8k16.
// smem: A[2][128][72]h | B[2][128][72]h = 73728 B  -> 2 CTAs/SM
// ============================================================================
#define GEMM_SMEM 73728

__global__ __launch_bounds__(256) void gemm_h(
    const __half* __restrict__ A,
    const __half* __restrict__ W0, const __half* __restrict__ W1, const __half* __restrict__ W2,
    const float* __restrict__ b0, const float* __restrict__ b1, const float* __restrict__ b2,
    float* __restrict__ C0, float* __restrict__ C1, float* __restrict__ C2)
{
    const int K = D_MODEL, Nn = D_MODEL;
    extern __shared__ __align__(16) __half smh[];
    __half* As = smh;              // [2][128][72]
    __half* Bs = smh + 2 * 9216;   // [2][128][72]
    const uint32_t sA = smem_u32(As), sB = smem_u32(Bs);

    const int tid = threadIdx.x;
    const int wid = tid >> 5, lane = tid & 31;
    const int g = lane >> 2, t = lane & 3;
    const int wm = wid >> 1, wn = wid & 1;
    const int bm = blockIdx.y * 128, bn = blockIdx.x * 128;

    const __half* Bw; const float* bias; float* C;
    if (blockIdx.z == 0)      { Bw = W0; bias = b0; C = C0; }
    else if (blockIdx.z == 1) { Bw = W1; bias = b1; C = C1; }
    else                      { Bw = W2; bias = b2; C = C2; }

    float acc[2][8][4];
    #pragma unroll
    for (int mi = 0; mi < 2; mi++)
        #pragma unroll
        for (int nj = 0; nj < 8; nj++)
            #pragma unroll
            for (int e = 0; e < 4; e++) acc[mi][nj][e] = 0.f;

    const int lr = tid >> 1;       // row 0..127
    const int lh = tid & 1;        // half-row (64B) selector
    const int nkt = K / 64;        // 24

    auto issue = [&](int kt) {
        const int st = kt & 1;
        const __half* Ap = A  + (size_t)(bm + lr) * K + kt * 64 + lh * 32;
        const __half* Bp = Bw + (size_t)(bn + lr) * K + kt * 64 + lh * 32;
        const uint32_t da = sA + st * 18432 + lr * 144 + lh * 64;
        const uint32_t db = sB + st * 18432 + lr * 144 + lh * 64;
        #pragma unroll
        for (int j = 0; j < 4; j++) {
            cp_async16(da + j * 16, Ap + j * 8);
            cp_async16(db + j * 16, Bp + j * 8);
        }
        CP_COMMIT();
    };

    issue(0);

    for (int kt = 0; kt < nkt; kt++) {
        __syncthreads();           // all warps done reading buffer (kt+1)&1
        if (kt + 1 < nkt) { issue(kt + 1); CP_WAIT1(); }
        else              { CP_WAIT0(); }
        __syncthreads();           // tile kt visible

        const uint32_t* as = (const uint32_t*)(As + (kt & 1) * 9216);
        const uint32_t* bs = (const uint32_t*)(Bs + (kt & 1) * 9216);
        #pragma unroll
        for (int kk = 0; kk < 4; kk++) {
            uint32_t a[2][4], b[8][2];
            #pragma unroll
            for (int mi = 0; mi < 2; mi++) {
                int row = wm * 32 + mi * 16 + g;
                a[mi][0] = as[row * 36 + kk * 8 + t];
                a[mi][1] = as[(row + 8) * 36 + kk * 8 + t];
                a[mi][2] = as[row * 36 + kk * 8 + t + 4];
                a[mi][3] = as[(row + 8) * 36 + kk * 8 + t + 4];
            }
            #pragma unroll
            for (int nj = 0; nj < 8; nj++) {
                int col = wn * 64 + nj * 8 + g;
                b[nj][0] = bs[col * 36 + kk * 8 + t];
                b[nj][1] = bs[col * 36 + kk * 8 + t + 4];
            }
            #pragma unroll
            for (int mi = 0; mi < 2; mi++)
                #pragma unroll
                for (int nj = 0; nj < 8; nj++)
                    mma_f16(acc[mi][nj], a[mi], b[nj][0], b[nj][1]);
        }
    }

    #pragma unroll
    for (int mi = 0; mi < 2; mi++) {
        #pragma unroll
        for (int nj = 0; nj < 8; nj++) {
            int row = bm + wm * 32 + mi * 16 + g;
            int col = bn + wn * 64 + nj * 8 + t * 2;
            float bb0 = __ldg(bias + col), bb1 = __ldg(bias + col + 1);
            *(float2*)(C + (size_t)row * Nn + col) =
                make_float2(acc[mi][nj][0] + bb0, acc[mi][nj][1] + bb1);
            *(float2*)(C + (size_t)(row + 8) * Nn + col) =
                make_float2(acc[mi][nj][2] + bb0, acc[mi][nj][3] + bb1);
        }
    }
}

// ============================================================================
// Fused RMS-norm (D=1536) + RoPE, fp32 in -> half out.
// grid = (L, 2): y==0 -> q (pre-scaled by 1/sqrt(d)), y==1 -> k.
// ============================================================================
__global__ __launch_bounds__(256) void rmsnorm_rope(
    const float* __restrict__ gq, const float* __restrict__ gk,
    const int* __restrict__ grid_sizes,
    const float* __restrict__ fcos, const float* __restrict__ fsin)
{
    const int row = blockIdx.x;
    const bool isK = (blockIdx.y != 0);
    const float* p = (isK ? g_k : g_q) + (size_t)row * D_MODEL;
    __half* ph = (isK ? g_kh : g_qh) + (size_t)row * D_MODEL;
    const float* gam = isK ? gk : gq;
    const float post = isK ? 1.0f : QK_SCALE;

    float ss = 0.f;
    for (int i = threadIdx.x; i < D_MODEL; i += 256) {
        float v = p[i];
        ss += v * v;
    }
    __shared__ float red[8];
    #pragma unroll
    for (int o = 16; o; o >>= 1) ss += __shfl_xor_sync(0xffffffffu, ss, o);
    if ((threadIdx.x & 31) == 0) red[threadIdx.x >> 5] = ss;
    __syncthreads();
    __shared__ float s_rms;
    if (threadIdx.x == 0) {
        float tot = 0.f;
        #pragma unroll
        for (int i = 0; i < 8; i++) tot += red[i];
        s_rms = rsqrtf(tot / (float)D_MODEL + 1e-6f);
    }
    __syncthreads();
    const float rms = s_rms;

    const int f = grid_sizes[0], h = grid_sizes[1], w = grid_sizes[2];
    const int sl = f * h * w;
    if (row < sl) {
        const int fi = row / (h * w);
        const int rem = row % (h * w);
        const int hi = rem / w, wi = rem % w;
        for (int pp = threadIdx.x; pp < N_HEADS * 64; pp += 256) {
            const int head = pp >> 6;
            const int j = pp & 63;
            const int pos = (j < 22) ? fi : ((j < 43) ? hi : wi);
            const float co = fcos[pos * 64 + j];
            const float si = fsin[pos * 64 + j];
            const int ci = head * HEAD_DIM + 2 * j;
            const float xr = p[ci] * rms * gam[ci];
            const float xi = p[ci + 1] * rms * gam[ci + 1];
            *(__half2*)(ph + ci) =
                __floats2half2_rn((xr * co - xi * si) * post, (xr * si + xi * co) * post);
        }
    } else {
        for (int i = threadIdx.x; i < D_MODEL; i += 256)
            ph[i] = __float2half_rn(p[i] * rms * gam[i] * post);
    }
}

// ============================================================================
// V transpose: v fp32 [seq][D] -> vt half [head][dim 128][seq 4096]
// grid (64, 12): 64-seq x 128-dim tile per block, 256 threads.
// ============================================================================
__global__ __launch_bounds__(256) void v_transpose(const float* __restrict__ v,
                                                   __half* __restrict__ vt)
{
    __shared__ __half T[128 * 72];
    const int s0 = blockIdx.x * 64, h = blockIdx.y;
    const int s = threadIdx.x >> 2, dg = threadIdx.x & 3;
    #pragma unroll
    for (int j = 0; j < 8; j++) {
        int d = dg * 32 + j * 4;
        float4 x = *(const float4*)(v + (size_t)(s0 + s) * D_MODEL + h * HEAD_DIM + d);
        T[(d + 0) * 72 + s] = __float2half_rn(x.x);
        T[(d + 1) * 72 + s] = __float2half_rn(x.y);
        T[(d + 2) * 72 + s] = __float2half_rn(x.z);
        T[(d + 3) * 72 + s] = __float2half_rn(x.w);
    }
    __syncthreads();
    #pragma unroll
    for (int it = 0; it < 4; it++) {
        int idx = it * 256 + threadIdx.x;
        int d = idx >> 3, c = idx & 7;
        uint4 u = *(uint4*)&T[d * 72 + c * 8];
        *(uint4*)(vt + ((size_t)(h * HEAD_DIM + d)) * L_SEQ + s0 + c * 8) = u;
    }
}

// ============================================================================
// fp16 flash attention: BM=128 x BN=64, d=128, 8 warps (256 thr).
// Q fragments in registers; K & V^T double-buffered via cp.async; fp32 softmax;
// P through smem as half2. Output half.
// smem bytes: K 2x17408 | Vt 2x18432 | Ps 18432 = 90112 B.
// ============================================================================
#define FA_SMEM 90112

__global__ __launch_bounds__(256) void flash_attn_h(
    const __half* __restrict__ q, const __half* __restrict__ k,
    const __half* __restrict__ vt, __half* __restrict__ att,
    const int* __restrict__ seq_lens)
{
    extern __shared__ __align__(16) uint32_t sw[];
    const uint32_t sbase = smem_u32(sw);

    const int tid = threadIdx.x, wid = tid >> 5, lane = tid & 31;
    const int g = lane >> 2, t = lane & 3;
    const int q0 = blockIdx.x * 128;
    const int head = blockIdx.y;
    const int seqlen = seq_lens[0];
    const int rowA = wid * 16 + g;

    // ---- stage Q (128x128 halves, stride 68 words) into K region, grab frags ----
    for (int i = tid; i < 128 * 16; i += 256) {
        int r = i >> 4, c = i & 15;
        uint4 u = *(const uint4*)(q + (size_t)(q0 + r) * D_MODEL + head * HEAD_DIM + c * 8);
        *(uint4*)((char*)sw + r * 272 + c * 16) = u;
    }
    __syncthreads();
    uint32_t Qa[8][4];
    #pragma unroll
    for (int kk = 0; kk < 8; kk++) {
        Qa[kk][0] = sw[rowA * 68 + kk * 8 + t];
        Qa[kk][1] = sw[(rowA + 8) * 68 + kk * 8 + t];
        Qa[kk][2] = sw[rowA * 68 + kk * 8 + t + 4];
        Qa[kk][3] = sw[(rowA + 8) * 68 + kk * 8 + t + 4];
    }
    __syncthreads();

    const int nkb = (seqlen + 63) >> 6;
    auto issue_kv = [&](int kb) {
        const int st = kb & 1;
        {   // K tile: 64 rows x 256B
            int r = tid >> 2;
            const __half* kp = k + (size_t)(kb * 64 + r) * D_MODEL + head * HEAD_DIM;
            uint32_t dst = sbase + st * 17408 + r * 272;
            #pragma unroll
            for (int j = 0; j < 4; j++) {
                int c = (tid & 3) + j * 4;
                cp_async16(dst + c * 16, kp + c * 8);
            }
        }
        {   // V^T tile: 128 dim-rows x 128B (64 keys)
            int r = tid >> 1;
            const __half* vp = vt + ((size_t)(head * HEAD_DIM + r)) * L_SEQ + kb * 64;
            uint32_t dst = sbase + 34816 + st * 18432 + r * 144;
            #pragma unroll
            for (int j = 0; j < 4; j++) {
                int c = (tid & 1) + j * 2;
                cp_async16(dst + c * 16, vp + c * 8);
            }
        }
        CP_COMMIT();
    };
    issue_kv(0);
    if (nkb > 1) issue_kv(1);

    float m0 = -INFINITY, m1 = -INFINITY, l0 = 0.f, l1 = 0.f;
    float O[16][4];
    #pragma unroll
    for (int nj = 0; nj < 16; nj++)
        #pragma unroll
        for (int e = 0; e < 4; e++) O[nj][e] = 0.f;

    uint32_t* Pw = sw + 17920;    // P halves, stride 36 words/row

    for (int kb = 0; kb < nkb; kb++) {
        if (kb + 1 < nkb) CP_WAIT1(); else CP_WAIT0();
        __syncthreads();

        const uint32_t* Kw = sw + (kb & 1) * 4352;          // K, stride 68 words
        const uint32_t* Vw = sw + 8704 + (kb & 1) * 4608;   // V^T, stride 36 words
        const int kbase = kb * 64;

        // S = Q @ K^T  (16x64 per warp; 8 kk x 8 nj m16n8k16)
        float S[8][4];
        #pragma unroll
        for (int nj = 0; nj < 8; nj++)
            #pragma unroll
            for (int e = 0; e < 4; e++) S[nj][e] = 0.f;

        #pragma unroll
        for (int kk = 0; kk < 8; kk++) {
            #pragma unroll
            for (int nj = 0; nj < 8; nj++) {
                uint32_t b0 = Kw[(nj * 8 + g) * 68 + kk * 8 + t];
                uint32_t b1 = Kw[(nj * 8 + g) * 68 + kk * 8 + t + 4];
                mma_f16(S[nj], Qa[kk], b0, b1);
            }
        }

        if (kbase + 64 > seqlen) {
            #pragma unroll
            for (int nj = 0; nj < 8; nj++) {
                int c0 = kbase + nj * 8 + t * 2;
                if (c0 >= seqlen)     { S[nj][0] = -1e30f; S[nj][2] = -1e30f; }
                if (c0 + 1 >= seqlen) { S[nj][1] = -1e30f; S[nj][3] = -1e30f; }
            }
        }

        // online softmax (fp32)
        float mx0 = -INFINITY, mx1 = -INFINITY;
        #pragma unroll
        for (int nj = 0; nj < 8; nj++) {
            mx0 = fmaxf(mx0, fmaxf(S[nj][0], S[nj][1]));
            mx1 = fmaxf(mx1, fmaxf(S[nj][2], S[nj][3]));
        }
        #pragma unroll
        for (int off = 1; off <= 2; off <<= 1) {
            mx0 = fmaxf(mx0, __shfl_xor_sync(0xffffffffu, mx0, off));
            mx1 = fmaxf(mx1, __shfl_xor_sync(0xffffffffu, mx1, off));
        }
        const float mn0 = fmaxf(m0, mx0), mn1 = fmaxf(m1, mx1);
        const float corr0 = __expf(m0 - mn0), corr1 = __expf(m1 - mn1);
        m0 = mn0; m1 = mn1;

        float rs0 = 0.f, rs1 = 0.f;
        #pragma unroll
        for (int nj = 0; nj < 8; nj++) {
            float p0 = __expf(S[nj][0] - mn0);
            float p1 = __expf(S[nj][1] - mn0);
            float p2 = __expf(S[nj][2] - mn1);
            float p3 = __expf(S[nj][3] - mn1);
            rs0 += p0 + p1;
            rs1 += p2 + p3;
            Pw[rowA * 36 + nj * 4 + t]       = h2u(__floats2half2_rn(p0, p1));
            Pw[(rowA + 8) * 36 + nj * 4 + t] = h2u(__floats2half2_rn(p2, p3));
        }
        #pragma unroll
        for (int off = 1; off <= 2; off <<= 1) {
            rs0 += __shfl_xor_sync(0xffffffffu, rs0, off);
            rs1 += __shfl_xor_sync(0xffffffffu, rs1, off);
        }
        l0 = l0 * corr0 + rs0;
        l1 = l1 * corr1 + rs1;
        #pragma unroll
        for (int nj = 0; nj < 16; nj++) {
            O[nj][0] *= corr0; O[nj][1] *= corr0;
            O[nj][2] *= corr1; O[nj][3] *= corr1;
        }
        __syncwarp();

        // O += P @ V  (4 kk x 16 nj m16n8k16)
        #pragma unroll
        for (int kk = 0; kk < 4; kk++) {
            uint32_t a[4];
            a[0] = Pw[rowA * 36 + kk * 8 + t];
            a[1] = Pw[(rowA + 8) * 36 + kk * 8 + t];
            a[2] = Pw[rowA * 36 + kk * 8 + t + 4];
            a[3] = Pw[(rowA + 8) * 36 + kk * 8 + t + 4];
            #pragma unroll
            for (int nj = 0; nj < 16; nj++) {
                uint32_t b0 = Vw[(nj * 8 + g) * 36 + kk * 8 + t];
                uint32_t b1 = Vw[(nj * 8 + g) * 36 + kk * 8 + t + 4];
                mma_f16(O[nj], a, b0, b1);
            }
        }

        __syncthreads();              // all warps done with buffers (kb&1)
        if (kb + 2 < nkb) issue_kv(kb + 2);
    }

    // epilogue: half output (consumed by Wo GEMM)
    const float inv0 = 1.f / l0, inv1 = 1.f / l1;
    #pragma unroll
    for (int nj = 0; nj < 16; nj++) {
        int gr = q0 + rowA;
        int col = head * HEAD_DIM + nj * 8 + t * 2;
        *(__half2*)(att + (size_t)gr * D_MODEL + col) =
            __floats2half2_rn(O[nj][0] * inv0, O[nj][1] * inv0);
        *(__half2*)(att + (size_t)(gr + 8) * D_MODEL + col) =
            __floats2half2_rn(O[nj][2] * inv1, O[nj][3] * inv1);
    }
}

// ============================================================================
// Launch
// ============================================================================
extern "C" void kernel_launch(void* const* d_in, const int* in_sizes, int n_in,
                              void* d_out, int out_size)
{
    (void)in_sizes; (void)n_in; (void)out_size;
    const float* x    = (const float*)d_in[0];
    const int* seqlen = (const int*)d_in[1];
    const int* gsizes = (const int*)d_in[2];
    const float* fcos = (const float*)d_in[3];
    const float* fsin = (const float*)d_in[4];
    const float* Wq = (const float*)d_in[5];
    const float* bq = (const float*)d_in[6];
    const float* Wk = (const float*)d_in[7];
    const float* bk = (const float*)d_in[8];
    const float* Wv = (const float*)d_in[9];
    const float* bv = (const float*)d_in[10];
    const float* Wo = (const float*)d_in[11];
    const float* bo = (const float*)d_in[12];
    const float* gq = (const float*)d_in[13];
    const float* gk = (const float*)d_in[14];
    float* out = (float*)d_out;

    float *pq, *pk, *pv;
    __half *pxh, *pqh, *pkh, *pvt, *pah, *pwq, *pwk, *pwv, *pwo;
    cudaGetSymbolAddress((void**)&pq,  g_q);
    cudaGetSymbolAddress((void**)&pk,  g_k);
    cudaGetSymbolAddress((void**)&pv,  g_v);
    cudaGetSymbolAddress((void**)&pxh, g_xh);
    cudaGetSymbolAddress((void**)&pqh, g_qh);
    cudaGetSymbolAddress((void**)&pkh, g_kh);
    cudaGetSymbolAddress((void**)&pvt, g_vt);
    cudaGetSymbolAddress((void**)&pah, g_ah);
    cudaGetSymbolAddress((void**)&pwq, g_wqh);
    cudaGetSymbolAddress((void**)&pwk, g_wkh);
    cudaGetSymbolAddress((void**)&pwv, g_wvh);
    cudaGetSymbolAddress((void**)&pwo, g_woh);

    cudaFuncSetAttribute(gemm_h, cudaFuncAttributeMaxDynamicSharedMemorySize, GEMM_SMEM);
    cudaFuncSetAttribute(flash_attn_h, cudaFuncAttributeMaxDynamicSharedMemorySize, FA_SMEM);

    const int nx4 = L_SEQ * D_MODEL / 4, nw4 = D_MODEL * D_MODEL / 4;
    cvt_half<<<(nx4 + 255) / 256, 256>>>(x,  pxh, nx4);
    cvt_half<<<(nw4 + 255) / 256, 256>>>(Wq, pwq, nw4);
    cvt_half<<<(nw4 + 255) / 256, 256>>>(Wk, pwk, nw4);
    cvt_half<<<(nw4 + 255) / 256, 256>>>(Wv, pwv, nw4);
    cvt_half<<<(nw4 + 255) / 256, 256>>>(Wo, pwo, nw4);

    // QKV projections (grid.z selects weight/output), fp32 outputs
    gemm_h<<<dim3(D_MODEL / 128, L_SEQ / 128, 3), 256, GEMM_SMEM>>>(
        pxh, pwq, pwk, pwv, bq, bk, bv, pq, pk, pv);

    rmsnorm_rope<<<dim3(L_SEQ, 2), 256>>>(gq, gk, gsizes, fcos, fsin);
    v_transpose<<<dim3(L_SEQ / 64, N_HEADS), 256>>>(pv, pvt);

    flash_attn_h<<<dim3(L_SEQ / 128, N_HEADS), 256, FA_SMEM>>>(pqh, pkh, pvt, pah, seqlen);

    gemm_h<<<dim3(D_MODEL / 128, L_SEQ / 128, 1), 256, GEMM_SMEM>>>(
        pah, pwo, pwo, pwo, bo, bo, bo, out, out, out);
}

// round 15
// speedup vs baseline: 2.4392x; 1.0243x over previous
#include <cuda_runtime.h>
#include <cuda_fp16.h>
#include <cstdint>
#include <math.h>

#define L_SEQ 4096
#define D_MODEL 1536
#define N_HEADS 12
#define HEAD_DIM 128
#define QK_SCALE 0.08838834764831845f   // 1/sqrt(128)

// Scratch (device globals; allocation-free per harness rules)
__device__ float  g_q [L_SEQ * D_MODEL];          // fp32 GEMM outputs
__device__ float  g_k [L_SEQ * D_MODEL];
__device__ float  g_v [L_SEQ * D_MODEL];
__device__ __half g_xh[L_SEQ * D_MODEL];          // half x
__device__ __half g_qh[L_SEQ * D_MODEL];          // half q (rms+rope+scale)
__device__ __half g_kh[L_SEQ * D_MODEL];          // half k (rms+rope)
__device__ __half g_vt[L_SEQ * D_MODEL];          // half V transposed [head][dim][seq]
__device__ __half g_ah[L_SEQ * D_MODEL];          // half attention output
__device__ __half g_wqh[D_MODEL * D_MODEL];
__device__ __half g_wkh[D_MODEL * D_MODEL];
__device__ __half g_wvh[D_MODEL * D_MODEL];
__device__ __half g_woh[D_MODEL * D_MODEL];

// ===================== helpers =====================
__device__ __forceinline__ uint32_t smem_u32(const void* p) {
    uint32_t a;
    asm("{ .reg .u64 t; cvta.to.shared.u64 t, %1; cvt.u32.u64 %0, t; }" : "=r"(a) : "l"(p));
    return a;
}

__device__ __forceinline__ void cp_async16(uint32_t dst, const void* src) {
    asm volatile("cp.async.cg.shared.global [%0], [%1], 16;" :: "r"(dst), "l"(src) : "memory");
}
#define CP_COMMIT() asm volatile("cp.async.commit_group;" ::: "memory")
#define CP_WAIT1()  asm volatile("cp.async.wait_group 1;" ::: "memory")
#define CP_WAIT0()  asm volatile("cp.async.wait_group 0;" ::: "memory")

// fp16 mma, fp32 accumulate
__device__ __forceinline__ void mma_f16(float* c, const uint32_t* a, uint32_t b0, uint32_t b1) {
    asm volatile(
        "mma.sync.aligned.m16n8k16.row.col.f32.f16.f16.f32 "
        "{%0,%1,%2,%3}, {%4,%5,%6,%7}, {%8,%9}, {%0,%1,%2,%3};"
        : "+f"(c[0]), "+f"(c[1]), "+f"(c[2]), "+f"(c[3])
        : "r"(a[0]), "r"(a[1]), "r"(a[2]), "r"(a[3]), "r"(b0), "r"(b1));
}

__device__ __forceinline__ void ldsm4(uint32_t* r, uint32_t addr) {
    asm volatile("ldmatrix.sync.aligned.m8n8.x4.shared.b16 {%0,%1,%2,%3}, [%4];"
                 : "=r"(r[0]), "=r"(r[1]), "=r"(r[2]), "=r"(r[3]) : "r"(addr));
}

__device__ __forceinline__ uint32_t h2u(__half2 h) { return *(uint32_t*)&h; }

// ============================================================================
// fp32 -> half convert
// ============================================================================
__global__ __launch_bounds__(256) void cvt_half(const float* __restrict__ s,
                                                __half* __restrict__ d, int n4)
{
    int i = blockIdx.x * 256 + threadIdx.x;
    if (i < n4) {
        float4 v = ((const float4*)s)[i];
        ((__half2*)d)[2 * i]     = __floats2half2_rn(v.x, v.y);
        ((__half2*)d)[2 * i + 1] = __floats2half2_rn(v.z, v.w);
    }
}

// ============================================================================
// fp16 GEMM: C[z][M,N] = A[M,K] @ W[z][N,K]^T + b[z][N]  (f32 accum)
// 128x128 tiles, k-tile = 64 halves (128B rows, 144B stride), 2-stage cp.async.
// 256 threads, 8 warps (4x2), warp tile 32x64, m16n8k16, ldmatrix fragments.
// smem: A[2][128][72]h | B[2][128][72]h = 73728 B
// ============================================================================
#define GEMM_SMEM 73728

__global__ __launch_bounds__(256) void gemm_h(
    const __half* __restrict__ A,
    const __half* __restrict__ W0, const __half* __restrict__ W1, const __half* __restrict__ W2,
    const float* __restrict__ b0, const float* __restrict__ b1, const float* __restrict__ b2,
    float* __restrict__ C0, float* __restrict__ C1, float* __restrict__ C2)
{
    const int K = D_MODEL, Nn = D_MODEL;
    extern __shared__ __align__(16) __half smh[];
    const uint32_t sA = smem_u32(smh);            // [2][128][72]
    const uint32_t sB = sA + 2 * 18432;           // [2][128][72]

    const int tid = threadIdx.x;
    const int wid = tid >> 5, lane = tid & 31;
    const int g = lane >> 2, t = lane & 3;
    const int wm = wid >> 1, wn = wid & 1;
    const int bm = blockIdx.y * 128, bn = blockIdx.x * 128;

    const __half* Bw; const float* bias; float* C;
    if (blockIdx.z == 0)      { Bw = W0; bias = b0; C = C0; }
    else if (blockIdx.z == 1) { Bw = W1; bias = b1; C = C1; }
    else                      { Bw = W2; bias = b2; C = C2; }

    float acc[2][8][4];
    #pragma unroll
    for (int mi = 0; mi < 2; mi++)
        #pragma unroll
        for (int nj = 0; nj < 8; nj++)
            #pragma unroll
            for (int e = 0; e < 4; e++) acc[mi][nj][e] = 0.f;

    // ldmatrix per-lane byte offsets (within a stage)
    const uint32_t a_off = (uint32_t)((wm * 32 + (lane & 15)) * 144 + ((lane & 16) ? 16 : 0));
    const int bcol = (lane & 7) | ((lane & 16) >> 1);
    const uint32_t bko = (lane & 8) ? 16u : 0u;
    const uint32_t b_off = (uint32_t)((wn * 64 + bcol) * 144) + bko;

    const int lr = tid >> 1;       // row 0..127
    const int lh = tid & 1;        // half-row (64B) selector
    const int nkt = K / 64;        // 24

    auto issue = [&](int kt) {
        const int st = kt & 1;
        const __half* Ap = A  + (size_t)(bm + lr) * K + kt * 64 + lh * 32;
        const __half* Bp = Bw + (size_t)(bn + lr) * K + kt * 64 + lh * 32;
        const uint32_t da = sA + st * 18432 + lr * 144 + lh * 64;
        const uint32_t db = sB + st * 18432 + lr * 144 + lh * 64;
        #pragma unroll
        for (int j = 0; j < 4; j++) {
            cp_async16(da + j * 16, Ap + j * 8);
            cp_async16(db + j * 16, Bp + j * 8);
        }
        CP_COMMIT();
    };

    issue(0);

    for (int kt = 0; kt < nkt; kt++) {
        __syncthreads();           // all warps done reading buffer (kt+1)&1
        if (kt + 1 < nkt) { issue(kt + 1); CP_WAIT1(); }
        else              { CP_WAIT0(); }
        __syncthreads();           // tile kt visible

        const uint32_t aS = sA + (kt & 1) * 18432;
        const uint32_t bS = sB + (kt & 1) * 18432;
        #pragma unroll
        for (int kk = 0; kk < 4; kk++) {
            uint32_t a0[4], a1[4];
            ldsm4(a0, aS + a_off + kk * 32);
            ldsm4(a1, aS + a_off + 16 * 144 + kk * 32);
            #pragma unroll
            for (int njp = 0; njp < 4; njp++) {
                uint32_t bb[4];
                ldsm4(bb, bS + b_off + njp * (16 * 144) + kk * 32);
                mma_f16(acc[0][2 * njp],     a0, bb[0], bb[1]);
                mma_f16(acc[0][2 * njp + 1], a0, bb[2], bb[3]);
                mma_f16(acc[1][2 * njp],     a1, bb[0], bb[1]);
                mma_f16(acc[1][2 * njp + 1], a1, bb[2], bb[3]);
            }
        }
    }

    #pragma unroll
    for (int mi = 0; mi < 2; mi++) {
        #pragma unroll
        for (int nj = 0; nj < 8; nj++) {
            int row = bm + wm * 32 + mi * 16 + g;
            int col = bn + wn * 64 + nj * 8 + t * 2;
            float bb0 = __ldg(bias + col), bb1 = __ldg(bias + col + 1);
            *(float2*)(C + (size_t)row * Nn + col) =
                make_float2(acc[mi][nj][0] + bb0, acc[mi][nj][1] + bb1);
            *(float2*)(C + (size_t)(row + 8) * Nn + col) =
                make_float2(acc[mi][nj][2] + bb0, acc[mi][nj][3] + bb1);
        }
    }
}

// ============================================================================
// Fused RMS-norm (D=1536) + RoPE, fp32 in -> half out.
// grid = (L, 2): y==0 -> q (pre-scaled by 1/sqrt(d)), y==1 -> k.
// ============================================================================
__global__ __launch_bounds__(256) void rmsnorm_rope(
    const float* __restrict__ gq, const float* __restrict__ gk,
    const int* __restrict__ grid_sizes,
    const float* __restrict__ fcos, const float* __restrict__ fsin)
{
    const int row = blockIdx.x;
    const bool isK = (blockIdx.y != 0);
    const float* p = (isK ? g_k : g_q) + (size_t)row * D_MODEL;
    __half* ph = (isK ? g_kh : g_qh) + (size_t)row * D_MODEL;
    const float* gam = isK ? gk : gq;
    const float post = isK ? 1.0f : QK_SCALE;

    float ss = 0.f;
    for (int i = threadIdx.x; i < D_MODEL; i += 256) {
        float v = p[i];
        ss += v * v;
    }
    __shared__ float red[8];
    #pragma unroll
    for (int o = 16; o; o >>= 1) ss += __shfl_xor_sync(0xffffffffu, ss, o);
    if ((threadIdx.x & 31) == 0) red[threadIdx.x >> 5] = ss;
    __syncthreads();
    __shared__ float s_rms;
    if (threadIdx.x == 0) {
        float tot = 0.f;
        #pragma unroll
        for (int i = 0; i < 8; i++) tot += red[i];
        s_rms = rsqrtf(tot / (float)D_MODEL + 1e-6f);
    }
    __syncthreads();
    const float rms = s_rms;

    const int f = grid_sizes[0], h = grid_sizes[1], w = grid_sizes[2];
    const int sl = f * h * w;
    if (row < sl) {
        const int fi = row / (h * w);
        const int rem = row % (h * w);
        const int hi = rem / w, wi = rem % w;
        for (int pp = threadIdx.x; pp < N_HEADS * 64; pp += 256) {
            const int head = pp >> 6;
            const int j = pp & 63;
            const int pos = (j < 22) ? fi : ((j < 43) ? hi : wi);
            const float co = fcos[pos * 64 + j];
            const float si = fsin[pos * 64 + j];
            const int ci = head * HEAD_DIM + 2 * j;
            const float xr = p[ci] * rms * gam[ci];
            const float xi = p[ci + 1] * rms * gam[ci + 1];
            *(__half2*)(ph + ci) =
                __floats2half2_rn((xr * co - xi * si) * post, (xr * si + xi * co) * post);
        }
    } else {
        for (int i = threadIdx.x; i < D_MODEL; i += 256)
            ph[i] = __float2half_rn(p[i] * rms * gam[i] * post);
    }
}

// ============================================================================
// V transpose: v fp32 [seq][D] -> vt half [head][dim 128][seq 4096]
// ============================================================================
__global__ __launch_bounds__(256) void v_transpose(const float* __restrict__ v,
                                                   __half* __restrict__ vt)
{
    __shared__ __half T[128 * 72];
    const int s0 = blockIdx.x * 64, h = blockIdx.y;
    const int s = threadIdx.x >> 2, dg = threadIdx.x & 3;
    #pragma unroll
    for (int j = 0; j < 8; j++) {
        int d = dg * 32 + j * 4;
        float4 x = *(const float4*)(v + (size_t)(s0 + s) * D_MODEL + h * HEAD_DIM + d);
        T[(d + 0) * 72 + s] = __float2half_rn(x.x);
        T[(d + 1) * 72 + s] = __float2half_rn(x.y);
        T[(d + 2) * 72 + s] = __float2half_rn(x.z);
        T[(d + 3) * 72 + s] = __float2half_rn(x.w);
    }
    __syncthreads();
    #pragma unroll
    for (int it = 0; it < 4; it++) {
        int idx = it * 256 + threadIdx.x;
        int d = idx >> 3, c = idx & 7;
        uint4 u = *(uint4*)&T[d * 72 + c * 8];
        *(uint4*)(vt + ((size_t)(h * HEAD_DIM + d)) * L_SEQ + s0 + c * 8) = u;
    }
}

// ============================================================================
// fp16 flash attention: BM=128 x BN=64, d=128, 8 warps (256 thr).
// Q fragments in registers; K & V^T double-buffered cp.async; ldmatrix frags;
// fp32 online softmax; P through smem as half2. Output half.
// smem bytes: K 2x17408 | Vt 2x18432 | Ps 18432 = 90112 B.
// ============================================================================
#define FA_SMEM 90112

__global__ __launch_bounds__(256) void flash_attn_h(
    const __half* __restrict__ q, const __half* __restrict__ k,
    const __half* __restrict__ vt, __half* __restrict__ att,
    const int* __restrict__ seq_lens)
{
    extern __shared__ __align__(16) uint32_t sw[];
    const uint32_t sbase = smem_u32(sw);

    const int tid = threadIdx.x, wid = tid >> 5, lane = tid & 31;
    const int g = lane >> 2, t = lane & 3;
    const int q0 = blockIdx.x * 128;
    const int head = blockIdx.y;
    const int seqlen = seq_lens[0];
    const int rowA = wid * 16 + g;

    // ---- stage Q (128x128 halves, 272B row stride) into K region, grab frags ----
    for (int i = tid; i < 128 * 16; i += 256) {
        int r = i >> 4, c = i & 15;
        uint4 u = *(const uint4*)(q + (size_t)(q0 + r) * D_MODEL + head * HEAD_DIM + c * 8);
        *(uint4*)((char*)sw + r * 272 + c * 16) = u;
    }
    __syncthreads();
    uint32_t Qa[8][4];
    {
        const uint32_t qa_off = (uint32_t)((wid * 16 + (lane & 15)) * 272 + ((lane & 16) ? 16 : 0));
        #pragma unroll
        for (int kk = 0; kk < 8; kk++) ldsm4(Qa[kk], sbase + qa_off + kk * 32);
    }
    __syncthreads();

    // ldmatrix per-lane offsets
    const int bcol = (lane & 7) | ((lane & 16) >> 1);
    const uint32_t bko = (lane & 8) ? 16u : 0u;
    const uint32_t kb_off = (uint32_t)(bcol * 272) + bko;               // K (stride 272B)
    const uint32_t vb_off = (uint32_t)(bcol * 144) + bko;               // V^T (stride 144B)
    const uint32_t pa_off = (uint32_t)((wid * 16 + (lane & 15)) * 144 + ((lane & 16) ? 16 : 0));

    const int nkb = (seqlen + 63) >> 6;
    auto issue_kv = [&](int kb) {
        const int st = kb & 1;
        {   // K tile: 64 rows x 256B
            int r = tid >> 2;
            const __half* kp = k + (size_t)(kb * 64 + r) * D_MODEL + head * HEAD_DIM;
            uint32_t dst = sbase + st * 17408 + r * 272;
            #pragma unroll
            for (int j = 0; j < 4; j++) {
                int c = (tid & 3) + j * 4;
                cp_async16(dst + c * 16, kp + c * 8);
            }
        }
        {   // V^T tile: 128 dim-rows x 128B (64 keys)
            int r = tid >> 1;
            const __half* vp = vt + ((size_t)(head * HEAD_DIM + r)) * L_SEQ + kb * 64;
            uint32_t dst = sbase + 34816 + st * 18432 + r * 144;
            #pragma unroll
            for (int j = 0; j < 4; j++) {
                int c = (tid & 1) + j * 2;
                cp_async16(dst + c * 16, vp + c * 8);
            }
        }
        CP_COMMIT();
    };
    issue_kv(0);
    if (nkb > 1) issue_kv(1);

    float m0 = -INFINITY, m1 = -INFINITY, l0 = 0.f, l1 = 0.f;
    float O[16][4];
    #pragma unroll
    for (int nj = 0; nj < 16; nj++)
        #pragma unroll
        for (int e = 0; e < 4; e++) O[nj][e] = 0.f;

    uint32_t* Pw = sw + 17920;    // P halves, stride 36 words/row
    const uint32_t psbase = sbase + 17920 * 4;

    for (int kb = 0; kb < nkb; kb++) {
        if (kb + 1 < nkb) CP_WAIT1(); else CP_WAIT0();
        __syncthreads();

        const uint32_t Kst = sbase + (kb & 1) * 17408;
        const uint32_t Vst = sbase + 34816 + (kb & 1) * 18432;
        const int kbase = kb * 64;

        // S = Q @ K^T  (16x64 per warp)
        float S[8][4];
        #pragma unroll
        for (int nj = 0; nj < 8; nj++)
            #pragma unroll
            for (int e = 0; e < 4; e++) S[nj][e] = 0.f;

        #pragma unroll
        for (int kk = 0; kk < 8; kk++) {
            #pragma unroll
            for (int njp = 0; njp < 4; njp++) {
                uint32_t bb[4];
                ldsm4(bb, Kst + kb_off + njp * (16 * 272) + kk * 32);
                mma_f16(S[2 * njp],     Qa[kk], bb[0], bb[1]);
                mma_f16(S[2 * njp + 1], Qa[kk], bb[2], bb[3]);
            }
        }

        if (kbase + 64 > seqlen) {
            #pragma unroll
            for (int nj = 0; nj < 8; nj++) {
                int c0 = kbase + nj * 8 + t * 2;
                if (c0 >= seqlen)     { S[nj][0] = -1e30f; S[nj][2] = -1e30f; }
                if (c0 + 1 >= seqlen) { S[nj][1] = -1e30f; S[nj][3] = -1e30f; }
            }
        }

        // online softmax (fp32)
        float mx0 = -INFINITY, mx1 = -INFINITY;
        #pragma unroll
        for (int nj = 0; nj < 8; nj++) {
            mx0 = fmaxf(mx0, fmaxf(S[nj][0], S[nj][1]));
            mx1 = fmaxf(mx1, fmaxf(S[nj][2], S[nj][3]));
        }
        #pragma unroll
        for (int off = 1; off <= 2; off <<= 1) {
            mx0 = fmaxf(mx0, __shfl_xor_sync(0xffffffffu, mx0, off));
            mx1 = fmaxf(mx1, __shfl_xor_sync(0xffffffffu, mx1, off));
        }
        const float mn0 = fmaxf(m0, mx0), mn1 = fmaxf(m1, mx1);
        const float corr0 = __expf(m0 - mn0), corr1 = __expf(m1 - mn1);
        m0 = mn0; m1 = mn1;

        float rs0 = 0.f, rs1 = 0.f;
        #pragma unroll
        for (int nj = 0; nj < 8; nj++) {
            float p0 = __expf(S[nj][0] - mn0);
            float p1 = __expf(S[nj][1] - mn0);
            float p2 = __expf(S[nj][2] - mn1);
            float p3 = __expf(S[nj][3] - mn1);
            rs0 += p0 + p1;
            rs1 += p2 + p3;
            Pw[rowA * 36 + nj * 4 + t]       = h2u(__floats2half2_rn(p0, p1));
            Pw[(rowA + 8) * 36 + nj * 4 + t] = h2u(__floats2half2_rn(p2, p3));
        }
        #pragma unroll
        for (int off = 1; off <= 2; off <<= 1) {
            rs0 += __shfl_xor_sync(0xffffffffu, rs0, off);
            rs1 += __shfl_xor_sync(0xffffffffu, rs1, off);
        }
        l0 = l0 * corr0 + rs0;
        l1 = l1 * corr1 + rs1;
        #pragma unroll
        for (int nj = 0; nj < 16; nj++) {
            O[nj][0] *= corr0; O[nj][1] *= corr0;
            O[nj][2] *= corr1; O[nj][3] *= corr1;
        }
        __syncwarp();

        // O += P @ V
        #pragma unroll
        for (int kk = 0; kk < 4; kk++) {
            uint32_t pa[4];
            ldsm4(pa, psbase + pa_off + kk * 32);
            #pragma unroll
            for (int njp = 0; njp < 8; njp++) {
                uint32_t vv[4];
                ldsm4(vv, Vst + vb_off + njp * (16 * 144) + kk * 32);
                mma_f16(O[2 * njp],     pa, vv[0], vv[1]);
                mma_f16(O[2 * njp + 1], pa, vv[2], vv[3]);
            }
        }

        __syncthreads();              // all warps done with buffers (kb&1)
        if (kb + 2 < nkb) issue_kv(kb + 2);
    }

    // epilogue: half output (consumed by Wo GEMM)
    const float inv0 = 1.f / l0, inv1 = 1.f / l1;
    #pragma unroll
    for (int nj = 0; nj < 16; nj++) {
        int gr = q0 + rowA;
        int col = head * HEAD_DIM + nj * 8 + t * 2;
        *(__half2*)(att + (size_t)gr * D_MODEL + col) =
            __floats2half2_rn(O[nj][0] * inv0, O[nj][1] * inv0);
        *(__half2*)(att + (size_t)(gr + 8) * D_MODEL + col) =
            __floats2half2_rn(O[nj][2] * inv1, O[nj][3] * inv1);
    }
}

// ============================================================================
// Launch
// ============================================================================
extern "C" void kernel_launch(void* const* d_in, const int* in_sizes, int n_in,
                              void* d_out, int out_size)
{
    (void)in_sizes; (void)n_in; (void)out_size;
    const float* x    = (const float*)d_in[0];
    const int* seqlen = (const int*)d_in[1];
    const int* gsizes = (const int*)d_in[2];
    const float* fcos = (const float*)d_in[3];
    const float* fsin = (const float*)d_in[4];
    const float* Wq = (const float*)d_in[5];
    const float* bq = (const float*)d_in[6];
    const float* Wk = (const float*)d_in[7];
    const float* bk = (const float*)d_in[8];
    const float* Wv = (const float*)d_in[9];
    const float* bv = (const float*)d_in[10];
    const float* Wo = (const float*)d_in[11];
    const float* bo = (const float*)d_in[12];
    const float* gq = (const float*)d_in[13];
    const float* gk = (const float*)d_in[14];
    float* out = (float*)d_out;

    float *pq, *pk, *pv;
    __half *pxh, *pqh, *pkh, *pvt, *pah, *pwq, *pwk, *pwv, *pwo;
    cudaGetSymbolAddress((void**)&pq,  g_q);
    cudaGetSymbolAddress((void**)&pk,  g_k);
    cudaGetSymbolAddress((void**)&pv,  g_v);
    cudaGetSymbolAddress((void**)&pxh, g_xh);
    cudaGetSymbolAddress((void**)&pqh, g_qh);
    cudaGetSymbolAddress((void**)&pkh, g_kh);
    cudaGetSymbolAddress((void**)&pvt, g_vt);
    cudaGetSymbolAddress((void**)&pah, g_ah);
    cudaGetSymbolAddress((void**)&pwq, g_wqh);
    cudaGetSymbolAddress((void**)&pwk, g_wkh);
    cudaGetSymbolAddress((void**)&pwv, g_wvh);
    cudaGetSymbolAddress((void**)&pwo, g_woh);

    cudaFuncSetAttribute(gemm_h, cudaFuncAttributeMaxDynamicSharedMemorySize, GEMM_SMEM);
    cudaFuncSetAttribute(flash_attn_h, cudaFuncAttributeMaxDynamicSharedMemorySize, FA_SMEM);

    const int nx4 = L_SEQ * D_MODEL / 4, nw4 = D_MODEL * D_MODEL / 4;
    cvt_half<<<(nx4 + 255) / 256, 256>>>(x,  pxh, nx4);
    cvt_half<<<(nw4 + 255) / 256, 256>>>(Wq, pwq, nw4);
    cvt_half<<<(nw4 + 255) / 256, 256>>>(Wk, pwk, nw4);
    cvt_half<<<(nw4 + 255) / 256, 256>>>(Wv, pwv, nw4);
    cvt_half<<<(nw4 + 255) / 256, 256>>>(Wo, pwo, nw4);

    // QKV projections (grid.z selects weight/output), fp32 outputs
    gemm_h<<<dim3(D_MODEL / 128, L_SEQ / 128, 3), 256, GEMM_SMEM>>>(
        pxh, pwq, pwk, pwv, bq, bk, bv, pq, pk, pv);

    rmsnorm_rope<<<dim3(L_SEQ, 2), 256>>>(gq, gk, gsizes, fcos, fsin);
    v_transpose<<<dim3(L_SEQ / 64, N_HEADS), 256>>>(pv, pvt);

    flash_attn_h<<<dim3(L_SEQ / 128, N_HEADS), 256, FA_SMEM>>>(pqh, pkh, pvt, pah, seqlen);

    gemm_h<<<dim3(D_MODEL / 128, L_SEQ / 128, 1), 256, GEMM_SMEM>>>(
        pah, pwo, pwo, pwo, bo, bo, bo, out, out, out);
}

// round 17
// speedup vs baseline: 2.5349x; 1.0392x over previous
#include <cuda_runtime.h>
#include <cuda_fp16.h>
#include <cstdint>
#include <math.h>

#define L_SEQ 4096
#define D_MODEL 1536
#define N_HEADS 12
#define HEAD_DIM 128
#define QK_SCALE 0.08838834764831845f   // 1/sqrt(128)

// Scratch (device globals; allocation-free per harness rules)
__device__ float  g_q [L_SEQ * D_MODEL];          // fp32 GEMM outputs
__device__ float  g_k [L_SEQ * D_MODEL];
__device__ float  g_v [L_SEQ * D_MODEL];
__device__ __half g_xh[L_SEQ * D_MODEL];          // half x
__device__ __half g_qh[L_SEQ * D_MODEL];          // half q (rms+rope+scale)
__device__ __half g_kh[L_SEQ * D_MODEL];          // half k (rms+rope)
__device__ __half g_vt[L_SEQ * D_MODEL];          // half V transposed [head][dim][seq]
__device__ __half g_ah[L_SEQ * D_MODEL];          // half attention output
__device__ __half g_wqh[D_MODEL * D_MODEL];
__device__ __half g_wkh[D_MODEL * D_MODEL];
__device__ __half g_wvh[D_MODEL * D_MODEL];
__device__ __half g_woh[D_MODEL * D_MODEL];

// ===================== helpers =====================
__device__ __forceinline__ uint32_t smem_u32(const void* p) {
    uint32_t a;
    asm("{ .reg .u64 t; cvta.to.shared.u64 t, %1; cvt.u32.u64 %0, t; }" : "=r"(a) : "l"(p));
    return a;
}

__device__ __forceinline__ void cp_async16(uint32_t dst, const void* src) {
    asm volatile("cp.async.cg.shared.global [%0], [%1], 16;" :: "r"(dst), "l"(src) : "memory");
}
#define CP_COMMIT() asm volatile("cp.async.commit_group;" ::: "memory")
#define CP_WAIT1()  asm volatile("cp.async.wait_group 1;" ::: "memory")
#define CP_WAIT0()  asm volatile("cp.async.wait_group 0;" ::: "memory")

// fp16 mma, fp32 accumulate
__device__ __forceinline__ void mma_f16(float* c, const uint32_t* a, uint32_t b0, uint32_t b1) {
    asm volatile(
        "mma.sync.aligned.m16n8k16.row.col.f32.f16.f16.f32 "
        "{%0,%1,%2,%3}, {%4,%5,%6,%7}, {%8,%9}, {%0,%1,%2,%3};"
        : "+f"(c[0]), "+f"(c[1]), "+f"(c[2]), "+f"(c[3])
        : "r"(a[0]), "r"(a[1]), "r"(a[2]), "r"(a[3]), "r"(b0), "r"(b1));
}

__device__ __forceinline__ void ldsm4(uint32_t* r, uint32_t addr) {
    asm volatile("ldmatrix.sync.aligned.m8n8.x4.shared.b16 {%0,%1,%2,%3}, [%4];"
                 : "=r"(r[0]), "=r"(r[1]), "=r"(r[2]), "=r"(r[3]) : "r"(addr));
}

__device__ __forceinline__ uint32_t h2u(__half2 h) { return *(uint32_t*)&h; }

// ============================================================================
// fp32 -> half converts
// ============================================================================
__global__ __launch_bounds__(256) void cvt_half(const float* __restrict__ s,
                                                __half* __restrict__ d, int n4)
{
    int i = blockIdx.x * 256 + threadIdx.x;
    if (i < n4) {
        float4 v = ((const float4*)s)[i];
        ((__half2*)d)[2 * i]     = __floats2half2_rn(v.x, v.y);
        ((__half2*)d)[2 * i + 1] = __floats2half2_rn(v.z, v.w);
    }
}

__global__ __launch_bounds__(256) void cvt_half_w(
    const float* __restrict__ w0, const float* __restrict__ w1,
    const float* __restrict__ w2, const float* __restrict__ w3,
    __half* __restrict__ d0, __half* __restrict__ d1,
    __half* __restrict__ d2, __half* __restrict__ d3, int n4)
{
    const float* s; __half* d;
    if (blockIdx.y == 0)      { s = w0; d = d0; }
    else if (blockIdx.y == 1) { s = w1; d = d1; }
    else if (blockIdx.y == 2) { s = w2; d = d2; }
    else                      { s = w3; d = d3; }
    int i = blockIdx.x * 256 + threadIdx.x;
    if (i < n4) {
        float4 v = ((const float4*)s)[i];
        ((__half2*)d)[2 * i]     = __floats2half2_rn(v.x, v.y);
        ((__half2*)d)[2 * i + 1] = __floats2half2_rn(v.z, v.w);
    }
}

// ============================================================================
// fp16 GEMM: C[z][M,N] = A[M,K] @ W[z][N,K]^T + b[z][N]  (f32 accum)
// 128x128 tiles, k-tile = 64 halves (128B rows, 144B stride), 2-stage cp.async.
// 256 threads, 8 warps (4x2), warp tile 32x64, m16n8k16, ldmatrix fragments.
// smem: A[2][128][72]h | B[2][128][72]h = 73728 B  (2 CTAs/SM)
// ============================================================================
#define GEMM_SMEM 73728

__global__ __launch_bounds__(256) void gemm_h(
    const __half* __restrict__ A,
    const __half* __restrict__ W0, const __half* __restrict__ W1, const __half* __restrict__ W2,
    const float* __restrict__ b0, const float* __restrict__ b1, const float* __restrict__ b2,
    float* __restrict__ C0, float* __restrict__ C1, float* __restrict__ C2)
{
    const int K = D_MODEL, Nn = D_MODEL;
    extern __shared__ __align__(16) __half smh[];
    const uint32_t sA = smem_u32(smh);            // [2][128][72]
    const uint32_t sB = sA + 2 * 18432;           // [2][128][72]

    const int tid = threadIdx.x;
    const int wid = tid >> 5, lane = tid & 31;
    const int g = lane >> 2, t = lane & 3;
    const int wm = wid >> 1, wn = wid & 1;
    const int bm = blockIdx.y * 128, bn = blockIdx.x * 128;

    const __half* Bw; const float* bias; float* C;
    if (blockIdx.z == 0)      { Bw = W0; bias = b0; C = C0; }
    else if (blockIdx.z == 1) { Bw = W1; bias = b1; C = C1; }
    else                      { Bw = W2; bias = b2; C = C2; }

    float acc[2][8][4];
    #pragma unroll
    for (int mi = 0; mi < 2; mi++)
        #pragma unroll
        for (int nj = 0; nj < 8; nj++)
            #pragma unroll
            for (int e = 0; e < 4; e++) acc[mi][nj][e] = 0.f;

    // ldmatrix per-lane byte offsets (within a stage)
    const uint32_t a_off = (uint32_t)((wm * 32 + (lane & 15)) * 144 + ((lane & 16) ? 16 : 0));
    const int bcol = (lane & 7) | ((lane & 16) >> 1);
    const uint32_t bko = (lane & 8) ? 16u : 0u;
    const uint32_t b_off = (uint32_t)((wn * 64 + bcol) * 144) + bko;

    const int lr = tid >> 1;       // row 0..127
    const int lh = tid & 1;        // half-row (64B) selector
    const int nkt = K / 64;        // 24

    auto issue = [&](int kt) {
        const int st = kt & 1;
        const __half* Ap = A  + (size_t)(bm + lr) * K + kt * 64 + lh * 32;
        const __half* Bp = Bw + (size_t)(bn + lr) * K + kt * 64 + lh * 32;
        const uint32_t da = sA + st * 18432 + lr * 144 + lh * 64;
        const uint32_t db = sB + st * 18432 + lr * 144 + lh * 64;
        #pragma unroll
        for (int j = 0; j < 4; j++) {
            cp_async16(da + j * 16, Ap + j * 8);
            cp_async16(db + j * 16, Bp + j * 8);
        }
        CP_COMMIT();
    };

    issue(0);

    for (int kt = 0; kt < nkt; kt++) {
        __syncthreads();           // all warps done reading buffer (kt+1)&1
        if (kt + 1 < nkt) { issue(kt + 1); CP_WAIT1(); }
        else              { CP_WAIT0(); }
        __syncthreads();           // tile kt visible

        const uint32_t aS = sA + (kt & 1) * 18432;
        const uint32_t bS = sB + (kt & 1) * 18432;
        #pragma unroll
        for (int kk = 0; kk < 4; kk++) {
            uint32_t a0[4], a1[4];
            ldsm4(a0, aS + a_off + kk * 32);
            ldsm4(a1, aS + a_off + 16 * 144 + kk * 32);
            #pragma unroll
            for (int njp = 0; njp < 4; njp++) {
                uint32_t bb[4];
                ldsm4(bb, bS + b_off + njp * (16 * 144) + kk * 32);
                mma_f16(acc[0][2 * njp],     a0, bb[0], bb[1]);
                mma_f16(acc[0][2 * njp + 1], a0, bb[2], bb[3]);
                mma_f16(acc[1][2 * njp],     a1, bb[0], bb[1]);
                mma_f16(acc[1][2 * njp + 1], a1, bb[2], bb[3]);
            }
        }
    }

    #pragma unroll
    for (int mi = 0; mi < 2; mi++) {
        #pragma unroll
        for (int nj = 0; nj < 8; nj++) {
            int row = bm + wm * 32 + mi * 16 + g;
            int col = bn + wn * 64 + nj * 8 + t * 2;
            float bb0 = __ldg(bias + col), bb1 = __ldg(bias + col + 1);
            *(float2*)(C + (size_t)row * Nn + col) =
                make_float2(acc[mi][nj][0] + bb0, acc[mi][nj][1] + bb1);
            *(float2*)(C + (size_t)(row + 8) * Nn + col) =
                make_float2(acc[mi][nj][2] + bb0, acc[mi][nj][3] + bb1);
        }
    }
}

// ============================================================================
// Fused RMS-norm (D=1536) + RoPE, fp32 in -> half out.
// grid = (L, 2): y==0 -> q (pre-scaled by 1/sqrt(d)), y==1 -> k.
// ============================================================================
__global__ __launch_bounds__(256) void rmsnorm_rope(
    const float* __restrict__ gq, const float* __restrict__ gk,
    const int* __restrict__ grid_sizes,
    const float* __restrict__ fcos, const float* __restrict__ fsin)
{
    const int row = blockIdx.x;
    const bool isK = (blockIdx.y != 0);
    const float* p = (isK ? g_k : g_q) + (size_t)row * D_MODEL;
    __half* ph = (isK ? g_kh : g_qh) + (size_t)row * D_MODEL;
    const float* gam = isK ? gk : gq;
    const float post = isK ? 1.0f : QK_SCALE;

    float ss = 0.f;
    for (int i = threadIdx.x; i < D_MODEL; i += 256) {
        float v = p[i];
        ss += v * v;
    }
    __shared__ float red[8];
    #pragma unroll
    for (int o = 16; o; o >>= 1) ss += __shfl_xor_sync(0xffffffffu, ss, o);
    if ((threadIdx.x & 31) == 0) red[threadIdx.x >> 5] = ss;
    __syncthreads();
    __shared__ float s_rms;
    if (threadIdx.x == 0) {
        float tot = 0.f;
        #pragma unroll
        for (int i = 0; i < 8; i++) tot += red[i];
        s_rms = rsqrtf(tot / (float)D_MODEL + 1e-6f);
    }
    __syncthreads();
    const float rms = s_rms;

    const int f = grid_sizes[0], h = grid_sizes[1], w = grid_sizes[2];
    const int sl = f * h * w;
    if (row < sl) {
        const int fi = row / (h * w);
        const int rem = row % (h * w);
        const int hi = rem / w, wi = rem % w;
        for (int pp = threadIdx.x; pp < N_HEADS * 64; pp += 256) {
            const int head = pp >> 6;
            const int j = pp & 63;
            const int pos = (j < 22) ? fi : ((j < 43) ? hi : wi);
            const float co = fcos[pos * 64 + j];
            const float si = fsin[pos * 64 + j];
            const int ci = head * HEAD_DIM + 2 * j;
            const float xr = p[ci] * rms * gam[ci];
            const float xi = p[ci + 1] * rms * gam[ci + 1];
            *(__half2*)(ph + ci) =
                __floats2half2_rn((xr * co - xi * si) * post, (xr * si + xi * co) * post);
        }
    } else {
        for (int i = threadIdx.x; i < D_MODEL; i += 256)
            ph[i] = __float2half_rn(p[i] * rms * gam[i] * post);
    }
}

// ============================================================================
// V transpose: v fp32 [seq][D] -> vt half [head][dim 128][seq 4096]
// ============================================================================
__global__ __launch_bounds__(256) void v_transpose(const float* __restrict__ v,
                                                   __half* __restrict__ vt)
{
    __shared__ __half T[128 * 72];
    const int s0 = blockIdx.x * 64, h = blockIdx.y;
    const int s = threadIdx.x >> 2, dg = threadIdx.x & 3;
    #pragma unroll
    for (int j = 0; j < 8; j++) {
        int d = dg * 32 + j * 4;
        float4 x = *(const float4*)(v + (size_t)(s0 + s) * D_MODEL + h * HEAD_DIM + d);
        T[(d + 0) * 72 + s] = __float2half_rn(x.x);
        T[(d + 1) * 72 + s] = __float2half_rn(x.y);
        T[(d + 2) * 72 + s] = __float2half_rn(x.z);
        T[(d + 3) * 72 + s] = __float2half_rn(x.w);
    }
    __syncthreads();
    #pragma unroll
    for (int it = 0; it < 4; it++) {
        int idx = it * 256 + threadIdx.x;
        int d = idx >> 3, c = idx & 7;
        uint4 u = *(uint4*)&T[d * 72 + c * 8];
        *(uint4*)(vt + ((size_t)(h * HEAD_DIM + d)) * L_SEQ + s0 + c * 8) = u;
    }
}

// ============================================================================
// fp16 flash attention: BM=128 x BN=64, d=128, 8 warps (256 thr).
// Q fragments in registers; 3-stage K & V^T cp.async ring, ONE sync/iter;
// P repacked register-to-register from the S accumulator (no smem trip);
// fp32 online softmax. Output half.
// smem bytes: K 3x17408 | Vt 3x18432 = 107520 B.
// ============================================================================
#define FA_SMEM 107520

__global__ __launch_bounds__(256) void flash_attn_h(
    const __half* __restrict__ q, const __half* __restrict__ k,
    const __half* __restrict__ vt, __half* __restrict__ att,
    const int* __restrict__ seq_lens)
{
    extern __shared__ __align__(16) uint32_t sw[];
    const uint32_t sbase = smem_u32(sw);

    const int tid = threadIdx.x, wid = tid >> 5, lane = tid & 31;
    const int g = lane >> 2, t = lane & 3;
    const int q0 = blockIdx.x * 128;
    const int head = blockIdx.y;
    const int seqlen = seq_lens[0];
    const int rowA = wid * 16 + g;

    // ---- stage Q (128 rows x 256B, 272B stride) into K-ring region, grab frags ----
    for (int i = tid; i < 128 * 16; i += 256) {
        int r = i >> 4, c = i & 15;
        uint4 u = *(const uint4*)(q + (size_t)(q0 + r) * D_MODEL + head * HEAD_DIM + c * 8);
        *(uint4*)((char*)sw + r * 272 + c * 16) = u;
    }
    __syncthreads();
    uint32_t Qa[8][4];
    {
        const uint32_t qa_off = (uint32_t)((wid * 16 + (lane & 15)) * 272 + ((lane & 16) ? 16 : 0));
        #pragma unroll
        for (int kk = 0; kk < 8; kk++) ldsm4(Qa[kk], sbase + qa_off + kk * 32);
    }
    __syncthreads();               // all warps own their Q frags; K-ring may be overwritten

    // ldmatrix per-lane offsets
    const int bcol = (lane & 7) | ((lane & 16) >> 1);
    const uint32_t bko = (lane & 8) ? 16u : 0u;
    const uint32_t kb_off = (uint32_t)(bcol * 272) + bko;               // K (stride 272B)
    const uint32_t vb_off = (uint32_t)(bcol * 144) + bko;               // V^T (stride 144B)

    const int nkb = (seqlen + 63) >> 6;
    auto issue_kv = [&](int kb) {
        const int st = kb % 3;
        {   // K tile: 64 rows x 256B
            int r = tid >> 2;
            const __half* kp = k + (size_t)(kb * 64 + r) * D_MODEL + head * HEAD_DIM;
            uint32_t dst = sbase + st * 17408 + r * 272;
            #pragma unroll
            for (int j = 0; j < 4; j++) {
                int c = (tid & 3) + j * 4;
                cp_async16(dst + c * 16, kp + c * 8);
            }
        }
        {   // V^T tile: 128 dim-rows x 128B (64 keys)
            int r = tid >> 1;
            const __half* vp = vt + ((size_t)(head * HEAD_DIM + r)) * L_SEQ + kb * 64;
            uint32_t dst = sbase + 52224 + st * 18432 + r * 144;
            #pragma unroll
            for (int j = 0; j < 4; j++) {
                int c = (tid & 1) + j * 2;
                cp_async16(dst + c * 16, vp + c * 8);
            }
        }
        CP_COMMIT();
    };
    issue_kv(0);
    if (nkb > 1) issue_kv(1);

    float m0 = -INFINITY, m1 = -INFINITY, l0 = 0.f, l1 = 0.f;
    float O[16][4];
    #pragma unroll
    for (int nj = 0; nj < 16; nj++)
        #pragma unroll
        for (int e = 0; e < 4; e++) O[nj][e] = 0.f;

    for (int kb = 0; kb < nkb; kb++) {
        if (kb + 1 < nkb) CP_WAIT1(); else CP_WAIT0();   // tile kb complete
        __syncthreads();                                 // visible to all; stage (kb+2)%3 free
        if (kb + 2 < nkb) issue_kv(kb + 2);              // overlaps the whole compute below

        const uint32_t Kst = sbase + (kb % 3) * 17408;
        const uint32_t Vst = sbase + 52224 + (kb % 3) * 18432;
        const int kbase = kb * 64;

        // S = Q @ K^T  (16x64 per warp)
        float S[8][4];
        #pragma unroll
        for (int nj = 0; nj < 8; nj++)
            #pragma unroll
            for (int e = 0; e < 4; e++) S[nj][e] = 0.f;

        #pragma unroll
        for (int kk = 0; kk < 8; kk++) {
            #pragma unroll
            for (int njp = 0; njp < 4; njp++) {
                uint32_t bb[4];
                ldsm4(bb, Kst + kb_off + njp * (16 * 272) + kk * 32);
                mma_f16(S[2 * njp],     Qa[kk], bb[0], bb[1]);
                mma_f16(S[2 * njp + 1], Qa[kk], bb[2], bb[3]);
            }
        }

        if (kbase + 64 > seqlen) {
            #pragma unroll
            for (int nj = 0; nj < 8; nj++) {
                int c0 = kbase + nj * 8 + t * 2;
                if (c0 >= seqlen)     { S[nj][0] = -1e30f; S[nj][2] = -1e30f; }
                if (c0 + 1 >= seqlen) { S[nj][1] = -1e30f; S[nj][3] = -1e30f; }
            }
        }

        // online softmax (fp32)
        float mx0 = -INFINITY, mx1 = -INFINITY;
        #pragma unroll
        for (int nj = 0; nj < 8; nj++) {
            mx0 = fmaxf(mx0, fmaxf(S[nj][0], S[nj][1]));
            mx1 = fmaxf(mx1, fmaxf(S[nj][2], S[nj][3]));
        }
        #pragma unroll
        for (int off = 1; off <= 2; off <<= 1) {
            mx0 = fmaxf(mx0, __shfl_xor_sync(0xffffffffu, mx0, off));
            mx1 = fmaxf(mx1, __shfl_xor_sync(0xffffffffu, mx1, off));
        }
        const float mn0 = fmaxf(m0, mx0), mn1 = fmaxf(m1, mx1);
        const float corr0 = __expf(m0 - mn0), corr1 = __expf(m1 - mn1);
        m0 = mn0; m1 = mn1;

        // P: exp in fp32, pack register-to-register into A-fragments for PV.
        // S[nj] accumulator layout == A-fragment layout of PV k-block nj/2
        // (a0=(g,2t),a1=(g+8,2t),a2=(g,2t+8),a3=(g+8,2t+8) mapping verified).
        uint32_t Pa[8][2];
        float rs0 = 0.f, rs1 = 0.f;
        #pragma unroll
        for (int nj = 0; nj < 8; nj++) {
            float p0 = __expf(S[nj][0] - mn0);
            float p1 = __expf(S[nj][1] - mn0);
            float p2 = __expf(S[nj][2] - mn1);
            float p3 = __expf(S[nj][3] - mn1);
            rs0 += p0 + p1;
            rs1 += p2 + p3;
            Pa[nj][0] = h2u(__floats2half2_rn(p0, p1));
            Pa[nj][1] = h2u(__floats2half2_rn(p2, p3));
        }
        #pragma unroll
        for (int off = 1; off <= 2; off <<= 1) {
            rs0 += __shfl_xor_sync(0xffffffffu, rs0, off);
            rs1 += __shfl_xor_sync(0xffffffffu, rs1, off);
        }
        l0 = l0 * corr0 + rs0;
        l1 = l1 * corr1 + rs1;
        #pragma unroll
        for (int nj = 0; nj < 16; nj++) {
            O[nj][0] *= corr0; O[nj][1] *= corr0;
            O[nj][2] *= corr1; O[nj][3] *= corr1;
        }

        // O += P @ V   (A-fragment = {Pa[2kk], Pa[2kk+1]})
        #pragma unroll
        for (int kk = 0; kk < 4; kk++) {
            uint32_t pa[4] = { Pa[2 * kk][0], Pa[2 * kk][1],
                               Pa[2 * kk + 1][0], Pa[2 * kk + 1][1] };
            #pragma unroll
            for (int njp = 0; njp < 8; njp++) {
                uint32_t vv[4];
                ldsm4(vv, Vst + vb_off + njp * (16 * 144) + kk * 32);
                mma_f16(O[2 * njp],     pa, vv[0], vv[1]);
                mma_f16(O[2 * njp + 1], pa, vv[2], vv[3]);
            }
        }
    }

    // epilogue: half output (consumed by Wo GEMM)
    const float inv0 = 1.f / l0, inv1 = 1.f / l1;
    #pragma unroll
    for (int nj = 0; nj < 16; nj++) {
        int gr = q0 + rowA;
        int col = head * HEAD_DIM + nj * 8 + t * 2;
        *(__half2*)(att + (size_t)gr * D_MODEL + col) =
            __floats2half2_rn(O[nj][0] * inv0, O[nj][1] * inv0);
        *(__half2*)(att + (size_t)(gr + 8) * D_MODEL + col) =
            __floats2half2_rn(O[nj][2] * inv1, O[nj][3] * inv1);
    }
}

// ============================================================================
// Launch
// ============================================================================
extern "C" void kernel_launch(void* const* d_in, const int* in_sizes, int n_in,
                              void* d_out, int out_size)
{
    (void)in_sizes; (void)n_in; (void)out_size;
    const float* x    = (const float*)d_in[0];
    const int* seqlen = (const int*)d_in[1];
    const int* gsizes = (const int*)d_in[2];
    const float* fcos = (const float*)d_in[3];
    const float* fsin = (const float*)d_in[4];
    const float* Wq = (const float*)d_in[5];
    const float* bq = (const float*)d_in[6];
    const float* Wk = (const float*)d_in[7];
    const float* bk = (const float*)d_in[8];
    const float* Wv = (const float*)d_in[9];
    const float* bv = (const float*)d_in[10];
    const float* Wo = (const float*)d_in[11];
    const float* bo = (const float*)d_in[12];
    const float* gq = (const float*)d_in[13];
    const float* gk = (const float*)d_in[14];
    float* out = (float*)d_out;

    float *pq, *pk, *pv;
    __half *pxh, *pqh, *pkh, *pvt, *pah, *pwq, *pwk, *pwv, *pwo;
    cudaGetSymbolAddress((void**)&pq,  g_q);
    cudaGetSymbolAddress((void**)&pk,  g_k);
    cudaGetSymbolAddress((void**)&pv,  g_v);
    cudaGetSymbolAddress((void**)&pxh, g_xh);
    cudaGetSymbolAddress((void**)&pqh, g_qh);
    cudaGetSymbolAddress((void**)&pkh, g_kh);
    cudaGetSymbolAddress((void**)&pvt, g_vt);
    cudaGetSymbolAddress((void**)&pah, g_ah);
    cudaGetSymbolAddress((void**)&pwq, g_wqh);
    cudaGetSymbolAddress((void**)&pwk, g_wkh);
    cudaGetSymbolAddress((void**)&pwv, g_wvh);
    cudaGetSymbolAddress((void**)&pwo, g_woh);

    cudaFuncSetAttribute(gemm_h, cudaFuncAttributeMaxDynamicSharedMemorySize, GEMM_SMEM);
    cudaFuncSetAttribute(flash_attn_h, cudaFuncAttributeMaxDynamicSharedMemorySize, FA_SMEM);

    const int nx4 = L_SEQ * D_MODEL / 4, nw4 = D_MODEL * D_MODEL / 4;
    cvt_half<<<(nx4 + 255) / 256, 256>>>(x, pxh, nx4);
    cvt_half_w<<<dim3((nw4 + 255) / 256, 4), 256>>>(
        Wq, Wk, Wv, Wo, pwq, pwk, pwv, pwo, nw4);

    // QKV projections (grid.z selects weight/output), fp32 outputs
    gemm_h<<<dim3(D_MODEL / 128, L_SEQ / 128, 3), 256, GEMM_SMEM>>>(
        pxh, pwq, pwk, pwv, bq, bk, bv, pq, pk, pv);

    rmsnorm_rope<<<dim3(L_SEQ, 2), 256>>>(gq, gk, gsizes, fcos, fsin);
    v_transpose<<<dim3(L_SEQ / 64, N_HEADS), 256>>>(pv, pvt);

    flash_attn_h<<<dim3(L_SEQ / 128, N_HEADS), 256, FA_SMEM>>>(pqh, pkh, pvt, pah, seqlen);

    gemm_h<<<dim3(D_MODEL / 128, L_SEQ / 128, 1), 256, GEMM_SMEM>>>(
        pah, pwo, pwo, pwo, bo, bo, bo, out, out, out);
}